// round 13
// baseline (speedup 1.0000x reference)
#include <cuda_runtime.h>
#include <cuda_bf16.h>
#include <cuda_fp16.h>
#include <cstdint>
#include <math.h>

// Problem constants
#define BATCH 2
#define SEQ   1024
#define HID   2048
#define NHEAD 16
#define HDIM  128
#define PASTL 1024
#define KVLEN 2048
#define MROWS 2048
#define NQKV  6144
#define QSCALE 0.08838834764831845f

// ---------------------------------------------------------------------------
// Scratch
// ---------------------------------------------------------------------------
__device__ float g_qkv [MROWS * NQKV];
__device__ float g_bias6144[NQKV];
__device__ __half g_A16[MROWS * HID];
__device__ __half g_Wqkvt[NQKV * HID];
__device__ __half g_Wot[HID * HID];
__device__ __half g_Q16[BATCH * NHEAD * SEQ * HDIM];
__device__ __half g_K16[BATCH * NHEAD * KVLEN * HDIM];
__device__ __half g_V16t[BATCH * NHEAD * HDIM * KVLEN];

// ---------------------------------------------------------------------------
// helpers
// ---------------------------------------------------------------------------
__device__ __forceinline__ uint32_t smem_u32(const void* p) {
    uint32_t a;
    asm("{ .reg .u64 t; cvta.to.shared.u64 t, %1; cvt.u32.u64 %0, t; }" : "=r"(a) : "l"(p));
    return a;
}
__device__ __forceinline__ void cp_async16(uint32_t dst, const void* src) {
    asm volatile("cp.async.cg.shared.global [%0], [%1], 16;" :: "r"(dst), "l"(src));
}
#define CP_ASYNC_COMMIT() asm volatile("cp.async.commit_group;" ::: "memory")
#define CP_ASYNC_WAIT2()  asm volatile("cp.async.wait_group 2;" ::: "memory")
#define CP_ASYNC_WAIT1()  asm volatile("cp.async.wait_group 1;" ::: "memory")
#define CP_ASYNC_WAIT0()  asm volatile("cp.async.wait_group 0;" ::: "memory")

__device__ __forceinline__ void mma_fp16(float& c0, float& c1, float& c2, float& c3,
                                         uint32_t a0, uint32_t a1, uint32_t a2, uint32_t a3,
                                         uint32_t b0, uint32_t b1) {
    asm volatile("mma.sync.aligned.m16n8k16.row.col.f32.f16.f16.f32 "
                 "{%0,%1,%2,%3}, {%4,%5,%6,%7}, {%8,%9}, {%0,%1,%2,%3};"
                 : "+f"(c0), "+f"(c1), "+f"(c2), "+f"(c3)
                 : "r"(a0), "r"(a1), "r"(a2), "r"(a3), "r"(b0), "r"(b1));
}
__device__ __forceinline__ void ldsm_x4(uint32_t* d, uint32_t addr) {
    asm volatile("ldmatrix.sync.aligned.m8n8.x4.shared.b16 {%0,%1,%2,%3}, [%4];"
                 : "=r"(d[0]), "=r"(d[1]), "=r"(d[2]), "=r"(d[3]) : "r"(addr));
}
__device__ __forceinline__ uint32_t pack_h2(float a, float b) {
    __half2 h = __floats2half2_rn(a, b);
    return *(uint32_t*)&h;
}

// ---------------------------------------------------------------------------
// Convert fp32 -> fp16 (packed)
// ---------------------------------------------------------------------------
__global__ void cvt_fp16_kernel(const float2* __restrict__ X, uint32_t* __restrict__ H, int n2) {
    int i = blockIdx.x * blockDim.x + threadIdx.x;
    if (i >= n2) return;
    float2 v = X[i];
    H[i] = pack_h2(v.x, v.y);
}

// ---------------------------------------------------------------------------
// Batched transpose + fp16-convert of 4 weight matrices; z==4 does bias concat
// ---------------------------------------------------------------------------
__global__ void transpose_cvt4_kernel(const float* __restrict__ Wq, const float* __restrict__ Wk,
                                      const float* __restrict__ Wv, const float* __restrict__ Wo,
                                      const float* __restrict__ bq, const float* __restrict__ bk,
                                      const float* __restrict__ bv) {
    if (blockIdx.z == 4) {
        // bias concat: grid.x*grid.y*256 threads cover 6144 (only first 24 blocks used)
        int i = (blockIdx.y * gridDim.x + blockIdx.x) * 256 + threadIdx.y * 32 + threadIdx.x;
        if (i < NQKV)
            g_bias6144[i] = (i < 2048) ? bq[i] : ((i < 4096) ? bk[i - 2048] : bv[i - 4096]);
        return;
    }
    __shared__ float t[32][33];
    const float* W;
    __half* T;
    int nofs;
    switch (blockIdx.z) {
        case 0:  W = Wq; T = g_Wqkvt; nofs = 0;    break;
        case 1:  W = Wk; T = g_Wqkvt; nofs = 2048; break;
        case 2:  W = Wv; T = g_Wqkvt; nofs = 4096; break;
        default: W = Wo; T = g_Wot;   nofs = 0;    break;
    }
    int bx = blockIdx.x * 32;
    int by = blockIdx.y * 32;
    int tx = threadIdx.x, ty = threadIdx.y;
    for (int r = ty; r < 32; r += 8)
        t[r][tx] = W[(size_t)(by + r) * HID + bx + tx];
    __syncthreads();
    for (int r = ty; r < 32; r += 8) {
        float v = t[tx][r];
        T[(size_t)(nofs + bx + r) * HID + by + tx] = __float2half_rn(v);
    }
}

// ---------------------------------------------------------------------------
// fp16 GEMM: CTA 128x128, 128 threads (4 warps 2x2, warp tile 64x64),
// BK=32, 3-stage cp.async, pitch 80B, 60 KB smem -> 3 CTAs/SM (regs<=170).
// ---------------------------------------------------------------------------
#define G8_PART  10240                  // 128 rows * 80B
#define G8_STAGE (2 * G8_PART)          // A + B = 20480
#define G8_SMEM  (3 * G8_STAGE)         // 61440

__device__ __forceinline__ void g8_load(const __half* __restrict__ A, const __half* __restrict__ B,
                                        int bm, int bn, int k0, uint32_t st, int tid) {
#pragma unroll
    for (int i = 0; i < 4; i++) {
        int c = i * 128 + tid;
        int row = c >> 2, cc = c & 3;
        cp_async16(st + (uint32_t)(row * 80 + cc * 16),
                   A + (size_t)(bm + row) * HID + k0 + cc * 8);
    }
#pragma unroll
    for (int i = 0; i < 4; i++) {
        int c = i * 128 + tid;
        int row = c >> 2, cc = c & 3;
        cp_async16(st + G8_PART + (uint32_t)(row * 80 + cc * 16),
                   B + (size_t)(bn + row) * HID + k0 + cc * 8);
    }
}

__global__ __launch_bounds__(128, 3)
void gemm_fp16_kernel(const __half* __restrict__ A, const __half* __restrict__ B,
                      const float* __restrict__ bias, float* __restrict__ C, int ldc) {
    extern __shared__ __align__(128) char smem[];
    const uint32_t sb = smem_u32(smem);
    const int tid = threadIdx.x;
    const int w = tid >> 5, lane = tid & 31;
    const int warp_m = w & 1, warp_n = w >> 1;
    const int bm = blockIdx.y * 128, bn = blockIdx.x * 128;
    const int r8 = lane & 7, ti = lane >> 3;
    const int gr = lane >> 2, tc = lane & 3;

    float acc[4][8][4];
#pragma unroll
    for (int a = 0; a < 4; a++)
#pragma unroll
        for (int b = 0; b < 8; b++)
#pragma unroll
            for (int c = 0; c < 4; c++) acc[a][b][c] = 0.f;

    // prologue: 3 stages
#pragma unroll
    for (int s = 0; s < 3; s++) {
        g8_load(A, B, bm, bn, s * 32, sb + s * G8_STAGE, tid);
        CP_ASYNC_COMMIT();
    }

    const int KITERS = HID / 32;   // 64
    int sidx = 0;
    for (int kt = 0; kt < KITERS; kt++) {
        uint32_t st = sb + (uint32_t)sidx * G8_STAGE;
        CP_ASYNC_WAIT2();
        __syncthreads();

#pragma unroll
        for (int ks = 0; ks < 2; ks++) {
            uint32_t bf[4][4];
#pragma unroll
            for (int np = 0; np < 4; np++) {
                uint32_t ba = st + G8_PART +
                              (uint32_t)((warp_n * 64 + np * 16 + r8 + ((ti >> 1) << 3)) * 80 +
                                         (ks * 16 + ((ti & 1) << 3)) * 2);
                ldsm_x4(bf[np], ba);
            }
#pragma unroll
            for (int mi = 0; mi < 4; mi++) {
                uint32_t af[4];
                uint32_t aa = st + (uint32_t)((warp_m * 64 + mi * 16 + r8 + ((ti & 1) << 3)) * 80 +
                                              (ks * 16 + ((ti >> 1) << 3)) * 2);
                ldsm_x4(af, aa);
#pragma unroll
                for (int np = 0; np < 4; np++) {
                    float* c0 = acc[mi][np * 2];
                    float* c1 = acc[mi][np * 2 + 1];
                    mma_fp16(c0[0], c0[1], c0[2], c0[3], af[0], af[1], af[2], af[3],
                             bf[np][0], bf[np][1]);
                    mma_fp16(c1[0], c1[1], c1[2], c1[3], af[0], af[1], af[2], af[3],
                             bf[np][2], bf[np][3]);
                }
            }
        }
        __syncthreads();
        if (kt + 3 < KITERS)
            g8_load(A, B, bm, bn, (kt + 3) * 32, st, tid);
        CP_ASYNC_COMMIT();
        sidx = (sidx == 2) ? 0 : sidx + 1;
    }

#pragma unroll
    for (int j = 0; j < 8; j++) {
        int col = bn + warp_n * 64 + j * 8 + tc * 2;
        float b0 = bias[col], b1 = bias[col + 1];
#pragma unroll
        for (int mi = 0; mi < 4; mi++) {
            int row0 = bm + warp_m * 64 + mi * 16 + gr;
            float* c = acc[mi][j];
            *(float2*)(C + (size_t)row0 * ldc + col) = make_float2(c[0] + b0, c[1] + b1);
            *(float2*)(C + (size_t)(row0 + 8) * ldc + col) = make_float2(c[2] + b0, c[3] + b1);
        }
    }
}

// ---------------------------------------------------------------------------
// RoPE + scatter: fp32 k/v to output caches; fp16 Q (scaled) and K caches.
// ---------------------------------------------------------------------------
__global__ void rope_scatter_kernel(float* __restrict__ outk, float* __restrict__ outv) {
    __shared__ float cs[64], sn[64];
    const int s = blockIdx.x;
    const int tid = threadIdx.x;
    if (tid < 64) {
        double invf = exp((double)tid * (-9.210340371976184 / 64.0));
        double ang = (double)s * invf;
        cs[tid] = (float)cos(ang);
        sn[tid] = (float)sin(ang);
    }
    __syncthreads();
    for (int e = tid; e < BATCH * NHEAD * 64; e += blockDim.x) {
        int d = e & 63;
        int h = (e >> 6) & (NHEAD - 1);
        int b = e >> 10;
        int bh = b * NHEAD + h;
        size_t r = ((size_t)(b * SEQ + s)) * NQKV + (size_t)h * HDIM + d;
        float c = cs[d], si = sn[d];
        float qlo = g_qkv[r],        qhi = g_qkv[r + 64];
        float klo = g_qkv[r + 2048], khi = g_qkv[r + 2048 + 64];

        float q0v = (qlo * c - qhi * si) * QSCALE;
        float q1v = (qhi * c + qlo * si) * QSCALE;
        size_t qo = ((size_t)bh * SEQ + s) * HDIM + d;
        g_Q16[qo]      = __float2half_rn(q0v);
        g_Q16[qo + 64] = __float2half_rn(q1v);

        float k0v = klo * c - khi * si;
        float k1v = khi * c + klo * si;
        size_t ko = ((size_t)bh * KVLEN + PASTL + s) * HDIM + d;
        outk[ko]      = k0v;
        outk[ko + 64] = k1v;
        g_K16[ko]      = __float2half_rn(k0v);
        g_K16[ko + 64] = __float2half_rn(k1v);

        outv[ko]      = g_qkv[r + 4096];
        outv[ko + 64] = g_qkv[r + 4096 + 64];
    }
}

// ---------------------------------------------------------------------------
// Copy past K/V into fp32 output caches + fp16 K cache
// ---------------------------------------------------------------------------
__global__ void copy_past_kernel(const float4* __restrict__ pk, const float4* __restrict__ pv,
                                 float4* __restrict__ outk, float4* __restrict__ outv) {
    int i = blockIdx.x * blockDim.x + threadIdx.x;
    if (i >= BATCH * NHEAD * PASTL * (HDIM / 4)) return;
    int col = i & 31;
    int p = (i >> 5) & (PASTL - 1);
    int bh = i >> 15;
    size_t src = ((size_t)bh * PASTL + p) * 32 + col;
    size_t dst = ((size_t)bh * KVLEN + p) * 32 + col;
    float4 kv = pk[src];
    outk[dst] = kv;
    outv[dst] = pv[src];
    uint2 hh = make_uint2(pack_h2(kv.x, kv.y), pack_h2(kv.z, kv.w));
    ((uint2*)g_K16)[dst] = hh;
}

// ---------------------------------------------------------------------------
// Transpose + fp16-convert V
// ---------------------------------------------------------------------------
__global__ void transpose_cvt_v_kernel(const float* __restrict__ outv) {
    __shared__ float t[32][33];
    int bh = blockIdx.z;
    int kv0 = blockIdx.x * 32, d0 = blockIdx.y * 32;
    const float* src = outv + (size_t)bh * KVLEN * HDIM;
    int tx = threadIdx.x, ty = threadIdx.y;
    for (int r = ty; r < 32; r += 8)
        t[r][tx] = src[(size_t)(kv0 + r) * HDIM + d0 + tx];
    __syncthreads();
    __half* dh = g_V16t + (size_t)bh * HDIM * KVLEN;
    for (int r = ty; r < 32; r += 8) {
        float v = t[tx][r];
        dh[(size_t)(d0 + r) * KVLEN + kv0 + tx] = __float2half_rn(v);
    }
}

// ---------------------------------------------------------------------------
// Flash attention, plain fp16 mma.sync (fp32 accumulate + fp32 softmax).
// ---------------------------------------------------------------------------
#define ATT_KPITCH 272
#define ATT_VPITCH 144
#define ATT_KPART (64 * ATT_KPITCH)
#define ATT_VPART (128 * ATT_VPITCH)
#define ATT_STAGE (ATT_KPART + ATT_VPART)
#define ATT_SMEM  (2 * ATT_STAGE)

__device__ __forceinline__ void att_load_tile(
    const __half* __restrict__ kg, const __half* __restrict__ vg,
    int kvb, uint32_t st, int tid) {
#pragma unroll
    for (int i = 0; i < 4; i++) {
        int c = i * 256 + tid;
        int row = c >> 4, cc = c & 15;
        cp_async16(st + (uint32_t)(row * ATT_KPITCH + cc * 16),
                   kg + (size_t)(kvb + row) * HDIM + cc * 8);
    }
#pragma unroll
    for (int i = 0; i < 4; i++) {
        int c = i * 256 + tid;
        int row = c >> 3, cc = c & 7;
        cp_async16(st + ATT_KPART + (uint32_t)(row * ATT_VPITCH + cc * 16),
                   vg + (size_t)row * KVLEN + kvb + cc * 8);
    }
}

__global__ __launch_bounds__(256, 1)
void attn_mma_kernel() {
    extern __shared__ __align__(128) char sm[];
    const uint32_t sb = smem_u32(sm);
    const int qt = gridDim.x - 1 - blockIdx.x;
    const int bh = blockIdx.y;
    const int b = bh >> 4, h = bh & 15;
    const int tid = threadIdx.x, w = tid >> 5, lane = tid & 31;
    const int gr = lane >> 2, tc = lane & 3;
    const int r8 = lane & 7, ti = lane >> 3;
    const int q0 = qt * 128;
    const int nt = 18 + 2 * qt;

    const __half* q_g = g_Q16 + ((size_t)bh * SEQ + q0) * HDIM;
    const __half* k_g = g_K16 + (size_t)bh * KVLEN * HDIM;
    const __half* v_g = g_V16t + (size_t)bh * HDIM * KVLEN;

#pragma unroll
    for (int i = 0; i < 8; i++) {
        int c = i * 256 + tid;
        int row = c >> 4, cc = c & 15;
        cp_async16(sb + (uint32_t)(row * ATT_KPITCH + cc * 16),
                   q_g + (size_t)row * HDIM + cc * 8);
    }
    CP_ASYNC_COMMIT();
    CP_ASYNC_WAIT0();
    __syncthreads();

    uint32_t qf[8][4];
#pragma unroll
    for (int t = 0; t < 8; t++) {
        uint32_t qa = sb + (uint32_t)((w * 16 + r8 + ((ti & 1) << 3)) * ATT_KPITCH +
                                      (t * 16 + ((ti >> 1) << 3)) * 2);
        ldsm_x4(qf[t], qa);
    }
    __syncthreads();

    att_load_tile(k_g, v_g, 0, sb, tid);
    CP_ASYNC_COMMIT();
    att_load_tile(k_g, v_g, 64, sb + ATT_STAGE, tid);
    CP_ASYNC_COMMIT();

    float m0 = -1e30f, m1 = -1e30f, l0 = 0.f, l1 = 0.f;
    float O[16][4];
#pragma unroll
    for (int i = 0; i < 16; i++)
#pragma unroll
        for (int c = 0; c < 4; c++) O[i][c] = 0.f;

    for (int j = 0; j < nt; j++) {
        uint32_t st = sb + (uint32_t)(j & 1) * ATT_STAGE;
        CP_ASYNC_WAIT1();
        __syncthreads();

        float S[8][4];
#pragma unroll
        for (int i = 0; i < 8; i++)
#pragma unroll
            for (int c = 0; c < 4; c++) S[i][c] = 0.f;

        const uint32_t kbase = st + (uint32_t)((r8 + ((ti >> 1) << 3)) * ATT_KPITCH +
                                               ((ti & 1) << 3) * 2);
#pragma unroll
        for (int kt = 0; kt < 8; kt++) {
#pragma unroll
            for (int p = 0; p < 4; p++) {
                uint32_t kb[4];
                ldsm_x4(kb, kbase + (uint32_t)(p * 16 * ATT_KPITCH + kt * 32));
                mma_fp16(S[2*p][0], S[2*p][1], S[2*p][2], S[2*p][3],
                         qf[kt][0], qf[kt][1], qf[kt][2], qf[kt][3], kb[0], kb[1]);
                mma_fp16(S[2*p+1][0], S[2*p+1][1], S[2*p+1][2], S[2*p+1][3],
                         qf[kt][0], qf[kt][1], qf[kt][2], qf[kt][3], kb[2], kb[3]);
            }
        }

        if (j >= nt - 2) {
            int qp0 = PASTL + q0 + w * 16 + gr;
#pragma unroll
            for (int i = 0; i < 8; i++) {
                int kvp = j * 64 + i * 8 + 2 * tc;
                if (kvp > qp0)         S[i][0] = -1e30f;
                if (kvp + 1 > qp0)     S[i][1] = -1e30f;
                if (kvp > qp0 + 8)     S[i][2] = -1e30f;
                if (kvp + 1 > qp0 + 8) S[i][3] = -1e30f;
            }
        }

        float mx0 = -1e30f, mx1 = -1e30f;
#pragma unroll
        for (int i = 0; i < 8; i++) {
            mx0 = fmaxf(mx0, fmaxf(S[i][0], S[i][1]));
            mx1 = fmaxf(mx1, fmaxf(S[i][2], S[i][3]));
        }
        mx0 = fmaxf(mx0, __shfl_xor_sync(0xffffffffu, mx0, 1));
        mx0 = fmaxf(mx0, __shfl_xor_sync(0xffffffffu, mx0, 2));
        mx1 = fmaxf(mx1, __shfl_xor_sync(0xffffffffu, mx1, 1));
        mx1 = fmaxf(mx1, __shfl_xor_sync(0xffffffffu, mx1, 2));
        float mn0 = fmaxf(m0, mx0), mn1 = fmaxf(m1, mx1);
        float a0 = __expf(m0 - mn0), a1 = __expf(m1 - mn1);
        m0 = mn0; m1 = mn1;

        float rs0 = 0.f, rs1 = 0.f;
        uint32_t pp[4][4];
#pragma unroll
        for (int i = 0; i < 8; i++) {
            float p0 = __expf(S[i][0] - mn0), p1 = __expf(S[i][1] - mn0);
            float p2 = __expf(S[i][2] - mn1), p3 = __expf(S[i][3] - mn1);
            rs0 += p0 + p1;
            rs1 += p2 + p3;
            int kvk = i >> 1, sel = (i & 1) * 2;
            pp[kvk][sel]     = pack_h2(p0, p1);
            pp[kvk][sel + 1] = pack_h2(p2, p3);
        }
        rs0 += __shfl_xor_sync(0xffffffffu, rs0, 1);
        rs0 += __shfl_xor_sync(0xffffffffu, rs0, 2);
        rs1 += __shfl_xor_sync(0xffffffffu, rs1, 1);
        rs1 += __shfl_xor_sync(0xffffffffu, rs1, 2);
        l0 = l0 * a0 + rs0;
        l1 = l1 * a1 + rs1;
#pragma unroll
        for (int i = 0; i < 16; i++) {
            O[i][0] *= a0; O[i][1] *= a0;
            O[i][2] *= a1; O[i][3] *= a1;
        }

        const uint32_t vbase = st + ATT_KPART +
                               (uint32_t)((r8 + ((ti >> 1) << 3)) * ATT_VPITCH +
                                          ((ti & 1) << 3) * 2);
#pragma unroll
        for (int kvk = 0; kvk < 4; kvk++) {
#pragma unroll
            for (int p = 0; p < 8; p++) {
                uint32_t vb[4];
                ldsm_x4(vb, vbase + (uint32_t)(p * 16 * ATT_VPITCH + kvk * 32));
                mma_fp16(O[2*p][0], O[2*p][1], O[2*p][2], O[2*p][3],
                         pp[kvk][0], pp[kvk][1], pp[kvk][2], pp[kvk][3], vb[0], vb[1]);
                mma_fp16(O[2*p+1][0], O[2*p+1][1], O[2*p+1][2], O[2*p+1][3],
                         pp[kvk][0], pp[kvk][1], pp[kvk][2], pp[kvk][3], vb[2], vb[3]);
            }
        }

        __syncthreads();
        if (j + 2 < nt)
            att_load_tile(k_g, v_g, (j + 2) * 64,
                          sb + (uint32_t)(j & 1) * ATT_STAGE, tid);
        CP_ASYNC_COMMIT();
    }

    float inv0 = 1.0f / l0, inv1 = 1.0f / l1;
    int row0 = b * SEQ + q0 + w * 16 + gr;
    size_t o0 = (size_t)row0 * HID + h * HDIM;
    size_t o1 = o0 + 8 * (size_t)HID;
#pragma unroll
    for (int dn = 0; dn < 16; dn++) {
        size_t i0 = o0 + dn * 8 + 2 * tc;
        size_t i1 = o1 + dn * 8 + 2 * tc;
        *(uint32_t*)(g_A16 + i0) = pack_h2(O[dn][0] * inv0, O[dn][1] * inv0);
        *(uint32_t*)(g_A16 + i1) = pack_h2(O[dn][2] * inv1, O[dn][3] * inv1);
    }
}

// ---------------------------------------------------------------------------
// kernel_launch  (launch index 2 = QKV GEMM, for ncu capture... index 3 kept)
// ---------------------------------------------------------------------------
extern "C" void kernel_launch(void* const* d_in, const int* in_sizes, int n_in,
                              void* d_out, int out_size) {
    const float* hidden = (const float*)d_in[0];
    const float* past_k = (const float*)d_in[2];
    const float* past_v = (const float*)d_in[3];
    const float* Wq = (const float*)d_in[4];
    const float* bq = (const float*)d_in[5];
    const float* Wk = (const float*)d_in[6];
    const float* bk = (const float*)d_in[7];
    const float* Wv = (const float*)d_in[8];
    const float* bv = (const float*)d_in[9];
    const float* Wo = (const float*)d_in[10];
    const float* bo = (const float*)d_in[11];

    float* out1 = (float*)d_out;
    float* outk = out1 + (size_t)MROWS * HID;
    float* outv = outk + (size_t)BATCH * NHEAD * KVLEN * HDIM;

    void *pqkv, *pbias, *pA16, *pWt, *pWo;
    cudaGetSymbolAddress(&pqkv, g_qkv);
    cudaGetSymbolAddress(&pbias, g_bias6144);
    cudaGetSymbolAddress(&pA16, g_A16);
    cudaGetSymbolAddress(&pWt, g_Wqkvt);
    cudaGetSymbolAddress(&pWo, g_Wot);

    cudaFuncSetAttribute(gemm_fp16_kernel, cudaFuncAttributeMaxDynamicSharedMemorySize, G8_SMEM);
    cudaFuncSetAttribute(attn_mma_kernel, cudaFuncAttributeMaxDynamicSharedMemorySize, ATT_SMEM);

    int n2 = MROWS * HID / 2;

    // 0: convert hidden to fp16
    cvt_fp16_kernel<<<(n2 + 255) / 256, 256>>>((const float2*)hidden, (uint32_t*)pA16, n2);
    // 1: weight transposes + bias concat in one launch (z=0..4)
    dim3 tblk(32, 8);
    transpose_cvt4_kernel<<<dim3(HID / 32, HID / 32, 5), tblk>>>(Wq, Wk, Wv, Wo, bq, bk, bv);
    // 2: dummy placeholder removed; keep ncu target at launch idx 3 via no-op split
    //    (QKV GEMM is now launch idx 2)
    // QKV GEMM (fp16, 3-stage, 3 CTA/SM)
    dim3 qkvgrid(NQKV / 128, MROWS / 128);
    gemm_fp16_kernel<<<qkvgrid, 128, G8_SMEM>>>((const __half*)pA16, (const __half*)pWt,
                                                (const float*)pbias, (float*)pqkv, NQKV);
    // RoPE + cache assembly
    rope_scatter_kernel<<<SEQ, 256>>>(outk, outv);
    // past copy
    int ncopy = BATCH * NHEAD * PASTL * (HDIM / 4);
    copy_past_kernel<<<(ncopy + 255) / 256, 256>>>((const float4*)past_k, (const float4*)past_v,
                                                   (float4*)outk, (float4*)outv);
    // V transpose/convert
    transpose_cvt_v_kernel<<<dim3(KVLEN / 32, HDIM / 32, BATCH * NHEAD), tblk>>>(outv);
    // attention
    dim3 agrid(SEQ / 128, BATCH * NHEAD);
    attn_mma_kernel<<<agrid, 256, ATT_SMEM>>>();
    // output projection
    dim3 ogrid(HID / 128, MROWS / 128);
    gemm_fp16_kernel<<<ogrid, 128, G8_SMEM>>>((const __half*)pA16, (const __half*)pWo,
                                              bo, out1, HID);
}

// round 14
// speedup vs baseline: 1.1312x; 1.1312x over previous
#include <cuda_runtime.h>
#include <cuda_bf16.h>
#include <cuda_fp16.h>
#include <cstdint>
#include <math.h>

// Problem constants
#define BATCH 2
#define SEQ   1024
#define HID   2048
#define NHEAD 16
#define HDIM  128
#define PASTL 1024
#define KVLEN 2048
#define MROWS 2048
#define NQKV  6144
#define QSCALE 0.08838834764831845f

// ---------------------------------------------------------------------------
// Scratch
// ---------------------------------------------------------------------------
__device__ float g_qkv [MROWS * NQKV];
__device__ float g_bias6144[NQKV];
__device__ __half g_A16[MROWS * HID];
__device__ __half g_Wqkvt[NQKV * HID];
__device__ __half g_Wot[HID * HID];
__device__ __half g_Q16[BATCH * NHEAD * SEQ * HDIM];
__device__ __half g_K16[BATCH * NHEAD * KVLEN * HDIM];
__device__ __half g_V16t[BATCH * NHEAD * HDIM * KVLEN];

// ---------------------------------------------------------------------------
// helpers
// ---------------------------------------------------------------------------
__device__ __forceinline__ uint32_t smem_u32(const void* p) {
    uint32_t a;
    asm("{ .reg .u64 t; cvta.to.shared.u64 t, %1; cvt.u32.u64 %0, t; }" : "=r"(a) : "l"(p));
    return a;
}
__device__ __forceinline__ void cp_async16(uint32_t dst, const void* src) {
    asm volatile("cp.async.cg.shared.global [%0], [%1], 16;" :: "r"(dst), "l"(src));
}
#define CP_ASYNC_COMMIT() asm volatile("cp.async.commit_group;" ::: "memory")
#define CP_ASYNC_WAIT2()  asm volatile("cp.async.wait_group 2;" ::: "memory")
#define CP_ASYNC_WAIT1()  asm volatile("cp.async.wait_group 1;" ::: "memory")
#define CP_ASYNC_WAIT0()  asm volatile("cp.async.wait_group 0;" ::: "memory")

__device__ __forceinline__ void mma_fp16(float& c0, float& c1, float& c2, float& c3,
                                         uint32_t a0, uint32_t a1, uint32_t a2, uint32_t a3,
                                         uint32_t b0, uint32_t b1) {
    asm volatile("mma.sync.aligned.m16n8k16.row.col.f32.f16.f16.f32 "
                 "{%0,%1,%2,%3}, {%4,%5,%6,%7}, {%8,%9}, {%0,%1,%2,%3};"
                 : "+f"(c0), "+f"(c1), "+f"(c2), "+f"(c3)
                 : "r"(a0), "r"(a1), "r"(a2), "r"(a3), "r"(b0), "r"(b1));
}
__device__ __forceinline__ void ldsm_x4(uint32_t* d, uint32_t addr) {
    asm volatile("ldmatrix.sync.aligned.m8n8.x4.shared.b16 {%0,%1,%2,%3}, [%4];"
                 : "=r"(d[0]), "=r"(d[1]), "=r"(d[2]), "=r"(d[3]) : "r"(addr));
}
__device__ __forceinline__ uint32_t pack_h2(float a, float b) {
    __half2 h = __floats2half2_rn(a, b);
    return *(uint32_t*)&h;
}

// ---------------------------------------------------------------------------
// Convert fp32 -> fp16 (packed)
// ---------------------------------------------------------------------------
__global__ void cvt_fp16_kernel(const float2* __restrict__ X, uint32_t* __restrict__ H, int n2) {
    int i = blockIdx.x * blockDim.x + threadIdx.x;
    if (i >= n2) return;
    float2 v = X[i];
    H[i] = pack_h2(v.x, v.y);
}

// ---------------------------------------------------------------------------
// Batched transpose + fp16-convert of 4 weight matrices; z==4 does bias concat
// ---------------------------------------------------------------------------
__global__ void transpose_cvt4_kernel(const float* __restrict__ Wq, const float* __restrict__ Wk,
                                      const float* __restrict__ Wv, const float* __restrict__ Wo,
                                      const float* __restrict__ bq, const float* __restrict__ bk,
                                      const float* __restrict__ bv) {
    if (blockIdx.z == 4) {
        int i = (blockIdx.y * gridDim.x + blockIdx.x) * 256 + threadIdx.y * 32 + threadIdx.x;
        if (i < NQKV)
            g_bias6144[i] = (i < 2048) ? bq[i] : ((i < 4096) ? bk[i - 2048] : bv[i - 4096]);
        return;
    }
    __shared__ float t[32][33];
    const float* W;
    __half* T;
    int nofs;
    switch (blockIdx.z) {
        case 0:  W = Wq; T = g_Wqkvt; nofs = 0;    break;
        case 1:  W = Wk; T = g_Wqkvt; nofs = 2048; break;
        case 2:  W = Wv; T = g_Wqkvt; nofs = 4096; break;
        default: W = Wo; T = g_Wot;   nofs = 0;    break;
    }
    int bx = blockIdx.x * 32;
    int by = blockIdx.y * 32;
    int tx = threadIdx.x, ty = threadIdx.y;
    for (int r = ty; r < 32; r += 8)
        t[r][tx] = W[(size_t)(by + r) * HID + bx + tx];
    __syncthreads();
    for (int r = ty; r < 32; r += 8) {
        float v = t[tx][r];
        T[(size_t)(nofs + bx + r) * HID + by + tx] = __float2half_rn(v);
    }
}

// ---------------------------------------------------------------------------
// fp16 GEMM: CTA 128x128, 128 threads (4 warps 2x2, warp tile 64x64),
// BK=32, 4-stage cp.async, CUTLASS-style single-sync schedule, 80 KB smem,
// 2 CTAs/SM, full 212 regs (no launch_bounds reg cap beyond occupancy 2).
// ---------------------------------------------------------------------------
#define G7_PART  10240                  // 128 rows * 80B
#define G7_STAGE (2 * G7_PART)          // A + B = 20480
#define G7_SMEM  (4 * G7_STAGE)         // 81920

__device__ __forceinline__ void g7_load(const __half* __restrict__ A, const __half* __restrict__ B,
                                        int bm, int bn, int k0, uint32_t st, int tid) {
#pragma unroll
    for (int i = 0; i < 4; i++) {
        int c = i * 128 + tid;
        int row = c >> 2, cc = c & 3;
        cp_async16(st + (uint32_t)(row * 80 + cc * 16),
                   A + (size_t)(bm + row) * HID + k0 + cc * 8);
    }
#pragma unroll
    for (int i = 0; i < 4; i++) {
        int c = i * 128 + tid;
        int row = c >> 2, cc = c & 3;
        cp_async16(st + G7_PART + (uint32_t)(row * 80 + cc * 16),
                   B + (size_t)(bn + row) * HID + k0 + cc * 8);
    }
}

__global__ __launch_bounds__(128, 2)
void gemm_fp16_kernel(const __half* __restrict__ A, const __half* __restrict__ B,
                      const float* __restrict__ bias, float* __restrict__ C, int ldc) {
    extern __shared__ __align__(128) char smem[];
    const uint32_t sb = smem_u32(smem);
    const int tid = threadIdx.x;
    const int w = tid >> 5, lane = tid & 31;
    const int warp_m = w & 1, warp_n = w >> 1;
    const int bm = blockIdx.y * 128, bn = blockIdx.x * 128;
    const int r8 = lane & 7, ti = lane >> 3;
    const int gr = lane >> 2, tc = lane & 3;

    float acc[4][8][4];
#pragma unroll
    for (int a = 0; a < 4; a++)
#pragma unroll
        for (int b = 0; b < 8; b++)
#pragma unroll
            for (int c = 0; c < 4; c++) acc[a][b][c] = 0.f;

    // prologue: fill 3 of 4 stages
#pragma unroll
    for (int s = 0; s < 3; s++) {
        g7_load(A, B, bm, bn, s * 32, sb + s * G7_STAGE, tid);
        CP_ASYNC_COMMIT();
    }

    const int KITERS = HID / 32;   // 64
    for (int kt = 0; kt < KITERS; kt++) {
        CP_ASYNC_WAIT2();
        __syncthreads();          // single barrier: stage kt ready; buffer (kt+3)&3 free

        if (kt + 3 < KITERS)
            g7_load(A, B, bm, bn, (kt + 3) * 32, sb + (uint32_t)((kt + 3) & 3) * G7_STAGE, tid);
        CP_ASYNC_COMMIT();

        uint32_t st = sb + (uint32_t)(kt & 3) * G7_STAGE;
#pragma unroll
        for (int ks = 0; ks < 2; ks++) {
            uint32_t bf[4][4];
#pragma unroll
            for (int np = 0; np < 4; np++) {
                uint32_t ba = st + G7_PART +
                              (uint32_t)((warp_n * 64 + np * 16 + r8 + ((ti >> 1) << 3)) * 80 +
                                         (ks * 16 + ((ti & 1) << 3)) * 2);
                ldsm_x4(bf[np], ba);
            }
#pragma unroll
            for (int mi = 0; mi < 4; mi++) {
                uint32_t af[4];
                uint32_t aa = st + (uint32_t)((warp_m * 64 + mi * 16 + r8 + ((ti & 1) << 3)) * 80 +
                                              (ks * 16 + ((ti >> 1) << 3)) * 2);
                ldsm_x4(af, aa);
#pragma unroll
                for (int np = 0; np < 4; np++) {
                    float* c0 = acc[mi][np * 2];
                    float* c1 = acc[mi][np * 2 + 1];
                    mma_fp16(c0[0], c0[1], c0[2], c0[3], af[0], af[1], af[2], af[3],
                             bf[np][0], bf[np][1]);
                    mma_fp16(c1[0], c1[1], c1[2], c1[3], af[0], af[1], af[2], af[3],
                             bf[np][2], bf[np][3]);
                }
            }
        }
    }

#pragma unroll
    for (int j = 0; j < 8; j++) {
        int col = bn + warp_n * 64 + j * 8 + tc * 2;
        float b0 = bias[col], b1 = bias[col + 1];
#pragma unroll
        for (int mi = 0; mi < 4; mi++) {
            int row0 = bm + warp_m * 64 + mi * 16 + gr;
            float* c = acc[mi][j];
            *(float2*)(C + (size_t)row0 * ldc + col) = make_float2(c[0] + b0, c[1] + b1);
            *(float2*)(C + (size_t)(row0 + 8) * ldc + col) = make_float2(c[2] + b0, c[3] + b1);
        }
    }
}

// ---------------------------------------------------------------------------
// RoPE + scatter: fp32 k/v to output caches; fp16 Q (scaled) and K caches.
// ---------------------------------------------------------------------------
__global__ void rope_scatter_kernel(float* __restrict__ outk, float* __restrict__ outv) {
    __shared__ float cs[64], sn[64];
    const int s = blockIdx.x;
    const int tid = threadIdx.x;
    if (tid < 64) {
        double invf = exp((double)tid * (-9.210340371976184 / 64.0));
        double ang = (double)s * invf;
        cs[tid] = (float)cos(ang);
        sn[tid] = (float)sin(ang);
    }
    __syncthreads();
    for (int e = tid; e < BATCH * NHEAD * 64; e += blockDim.x) {
        int d = e & 63;
        int h = (e >> 6) & (NHEAD - 1);
        int b = e >> 10;
        int bh = b * NHEAD + h;
        size_t r = ((size_t)(b * SEQ + s)) * NQKV + (size_t)h * HDIM + d;
        float c = cs[d], si = sn[d];
        float qlo = g_qkv[r],        qhi = g_qkv[r + 64];
        float klo = g_qkv[r + 2048], khi = g_qkv[r + 2048 + 64];

        float q0v = (qlo * c - qhi * si) * QSCALE;
        float q1v = (qhi * c + qlo * si) * QSCALE;
        size_t qo = ((size_t)bh * SEQ + s) * HDIM + d;
        g_Q16[qo]      = __float2half_rn(q0v);
        g_Q16[qo + 64] = __float2half_rn(q1v);

        float k0v = klo * c - khi * si;
        float k1v = khi * c + klo * si;
        size_t ko = ((size_t)bh * KVLEN + PASTL + s) * HDIM + d;
        outk[ko]      = k0v;
        outk[ko + 64] = k1v;
        g_K16[ko]      = __float2half_rn(k0v);
        g_K16[ko + 64] = __float2half_rn(k1v);

        outv[ko]      = g_qkv[r + 4096];
        outv[ko + 64] = g_qkv[r + 4096 + 64];
    }
}

// ---------------------------------------------------------------------------
// Copy past K/V into fp32 output caches + fp16 K cache
// ---------------------------------------------------------------------------
__global__ void copy_past_kernel(const float4* __restrict__ pk, const float4* __restrict__ pv,
                                 float4* __restrict__ outk, float4* __restrict__ outv) {
    int i = blockIdx.x * blockDim.x + threadIdx.x;
    if (i >= BATCH * NHEAD * PASTL * (HDIM / 4)) return;
    int col = i & 31;
    int p = (i >> 5) & (PASTL - 1);
    int bh = i >> 15;
    size_t src = ((size_t)bh * PASTL + p) * 32 + col;
    size_t dst = ((size_t)bh * KVLEN + p) * 32 + col;
    float4 kv = pk[src];
    outk[dst] = kv;
    outv[dst] = pv[src];
    uint2 hh = make_uint2(pack_h2(kv.x, kv.y), pack_h2(kv.z, kv.w));
    ((uint2*)g_K16)[dst] = hh;
}

// ---------------------------------------------------------------------------
// Transpose + fp16-convert V
// ---------------------------------------------------------------------------
__global__ void transpose_cvt_v_kernel(const float* __restrict__ outv) {
    __shared__ float t[32][33];
    int bh = blockIdx.z;
    int kv0 = blockIdx.x * 32, d0 = blockIdx.y * 32;
    const float* src = outv + (size_t)bh * KVLEN * HDIM;
    int tx = threadIdx.x, ty = threadIdx.y;
    for (int r = ty; r < 32; r += 8)
        t[r][tx] = src[(size_t)(kv0 + r) * HDIM + d0 + tx];
    __syncthreads();
    __half* dh = g_V16t + (size_t)bh * HDIM * KVLEN;
    for (int r = ty; r < 32; r += 8) {
        float v = t[tx][r];
        dh[(size_t)(d0 + r) * KVLEN + kv0 + tx] = __float2half_rn(v);
    }
}

// ---------------------------------------------------------------------------
// Flash attention, plain fp16 mma.sync (fp32 accumulate + fp32 softmax).
// ---------------------------------------------------------------------------
#define ATT_KPITCH 272
#define ATT_VPITCH 144
#define ATT_KPART (64 * ATT_KPITCH)
#define ATT_VPART (128 * ATT_VPITCH)
#define ATT_STAGE (ATT_KPART + ATT_VPART)
#define ATT_SMEM  (2 * ATT_STAGE)

__device__ __forceinline__ void att_load_tile(
    const __half* __restrict__ kg, const __half* __restrict__ vg,
    int kvb, uint32_t st, int tid) {
#pragma unroll
    for (int i = 0; i < 4; i++) {
        int c = i * 256 + tid;
        int row = c >> 4, cc = c & 15;
        cp_async16(st + (uint32_t)(row * ATT_KPITCH + cc * 16),
                   kg + (size_t)(kvb + row) * HDIM + cc * 8);
    }
#pragma unroll
    for (int i = 0; i < 4; i++) {
        int c = i * 256 + tid;
        int row = c >> 3, cc = c & 7;
        cp_async16(st + ATT_KPART + (uint32_t)(row * ATT_VPITCH + cc * 16),
                   vg + (size_t)row * KVLEN + kvb + cc * 8);
    }
}

__global__ __launch_bounds__(256, 1)
void attn_mma_kernel() {
    extern __shared__ __align__(128) char sm[];
    const uint32_t sb = smem_u32(sm);
    const int qt = gridDim.x - 1 - blockIdx.x;
    const int bh = blockIdx.y;
    const int b = bh >> 4, h = bh & 15;
    const int tid = threadIdx.x, w = tid >> 5, lane = tid & 31;
    const int gr = lane >> 2, tc = lane & 3;
    const int r8 = lane & 7, ti = lane >> 3;
    const int q0 = qt * 128;
    const int nt = 18 + 2 * qt;

    const __half* q_g = g_Q16 + ((size_t)bh * SEQ + q0) * HDIM;
    const __half* k_g = g_K16 + (size_t)bh * KVLEN * HDIM;
    const __half* v_g = g_V16t + (size_t)bh * HDIM * KVLEN;

#pragma unroll
    for (int i = 0; i < 8; i++) {
        int c = i * 256 + tid;
        int row = c >> 4, cc = c & 15;
        cp_async16(sb + (uint32_t)(row * ATT_KPITCH + cc * 16),
                   q_g + (size_t)row * HDIM + cc * 8);
    }
    CP_ASYNC_COMMIT();
    CP_ASYNC_WAIT0();
    __syncthreads();

    uint32_t qf[8][4];
#pragma unroll
    for (int t = 0; t < 8; t++) {
        uint32_t qa = sb + (uint32_t)((w * 16 + r8 + ((ti & 1) << 3)) * ATT_KPITCH +
                                      (t * 16 + ((ti >> 1) << 3)) * 2);
        ldsm_x4(qf[t], qa);
    }
    __syncthreads();

    att_load_tile(k_g, v_g, 0, sb, tid);
    CP_ASYNC_COMMIT();
    att_load_tile(k_g, v_g, 64, sb + ATT_STAGE, tid);
    CP_ASYNC_COMMIT();

    float m0 = -1e30f, m1 = -1e30f, l0 = 0.f, l1 = 0.f;
    float O[16][4];
#pragma unroll
    for (int i = 0; i < 16; i++)
#pragma unroll
        for (int c = 0; c < 4; c++) O[i][c] = 0.f;

    for (int j = 0; j < nt; j++) {
        uint32_t st = sb + (uint32_t)(j & 1) * ATT_STAGE;
        CP_ASYNC_WAIT1();
        __syncthreads();

        float S[8][4];
#pragma unroll
        for (int i = 0; i < 8; i++)
#pragma unroll
            for (int c = 0; c < 4; c++) S[i][c] = 0.f;

        const uint32_t kbase = st + (uint32_t)((r8 + ((ti >> 1) << 3)) * ATT_KPITCH +
                                               ((ti & 1) << 3) * 2);
#pragma unroll
        for (int kt = 0; kt < 8; kt++) {
#pragma unroll
            for (int p = 0; p < 4; p++) {
                uint32_t kb[4];
                ldsm_x4(kb, kbase + (uint32_t)(p * 16 * ATT_KPITCH + kt * 32));
                mma_fp16(S[2*p][0], S[2*p][1], S[2*p][2], S[2*p][3],
                         qf[kt][0], qf[kt][1], qf[kt][2], qf[kt][3], kb[0], kb[1]);
                mma_fp16(S[2*p+1][0], S[2*p+1][1], S[2*p+1][2], S[2*p+1][3],
                         qf[kt][0], qf[kt][1], qf[kt][2], qf[kt][3], kb[2], kb[3]);
            }
        }

        if (j >= nt - 2) {
            int qp0 = PASTL + q0 + w * 16 + gr;
#pragma unroll
            for (int i = 0; i < 8; i++) {
                int kvp = j * 64 + i * 8 + 2 * tc;
                if (kvp > qp0)         S[i][0] = -1e30f;
                if (kvp + 1 > qp0)     S[i][1] = -1e30f;
                if (kvp > qp0 + 8)     S[i][2] = -1e30f;
                if (kvp + 1 > qp0 + 8) S[i][3] = -1e30f;
            }
        }

        float mx0 = -1e30f, mx1 = -1e30f;
#pragma unroll
        for (int i = 0; i < 8; i++) {
            mx0 = fmaxf(mx0, fmaxf(S[i][0], S[i][1]));
            mx1 = fmaxf(mx1, fmaxf(S[i][2], S[i][3]));
        }
        mx0 = fmaxf(mx0, __shfl_xor_sync(0xffffffffu, mx0, 1));
        mx0 = fmaxf(mx0, __shfl_xor_sync(0xffffffffu, mx0, 2));
        mx1 = fmaxf(mx1, __shfl_xor_sync(0xffffffffu, mx1, 1));
        mx1 = fmaxf(mx1, __shfl_xor_sync(0xffffffffu, mx1, 2));
        float mn0 = fmaxf(m0, mx0), mn1 = fmaxf(m1, mx1);
        float a0 = __expf(m0 - mn0), a1 = __expf(m1 - mn1);
        m0 = mn0; m1 = mn1;

        float rs0 = 0.f, rs1 = 0.f;
        uint32_t pp[4][4];
#pragma unroll
        for (int i = 0; i < 8; i++) {
            float p0 = __expf(S[i][0] - mn0), p1 = __expf(S[i][1] - mn0);
            float p2 = __expf(S[i][2] - mn1), p3 = __expf(S[i][3] - mn1);
            rs0 += p0 + p1;
            rs1 += p2 + p3;
            int kvk = i >> 1, sel = (i & 1) * 2;
            pp[kvk][sel]     = pack_h2(p0, p1);
            pp[kvk][sel + 1] = pack_h2(p2, p3);
        }
        rs0 += __shfl_xor_sync(0xffffffffu, rs0, 1);
        rs0 += __shfl_xor_sync(0xffffffffu, rs0, 2);
        rs1 += __shfl_xor_sync(0xffffffffu, rs1, 1);
        rs1 += __shfl_xor_sync(0xffffffffu, rs1, 2);
        l0 = l0 * a0 + rs0;
        l1 = l1 * a1 + rs1;
#pragma unroll
        for (int i = 0; i < 16; i++) {
            O[i][0] *= a0; O[i][1] *= a0;
            O[i][2] *= a1; O[i][3] *= a1;
        }

        const uint32_t vbase = st + ATT_KPART +
                               (uint32_t)((r8 + ((ti >> 1) << 3)) * ATT_VPITCH +
                                          ((ti & 1) << 3) * 2);
#pragma unroll
        for (int kvk = 0; kvk < 4; kvk++) {
#pragma unroll
            for (int p = 0; p < 8; p++) {
                uint32_t vb[4];
                ldsm_x4(vb, vbase + (uint32_t)(p * 16 * ATT_VPITCH + kvk * 32));
                mma_fp16(O[2*p][0], O[2*p][1], O[2*p][2], O[2*p][3],
                         pp[kvk][0], pp[kvk][1], pp[kvk][2], pp[kvk][3], vb[0], vb[1]);
                mma_fp16(O[2*p+1][0], O[2*p+1][1], O[2*p+1][2], O[2*p+1][3],
                         pp[kvk][0], pp[kvk][1], pp[kvk][2], pp[kvk][3], vb[2], vb[3]);
            }
        }

        __syncthreads();
        if (j + 2 < nt)
            att_load_tile(k_g, v_g, (j + 2) * 64,
                          sb + (uint32_t)(j & 1) * ATT_STAGE, tid);
        CP_ASYNC_COMMIT();
    }

    float inv0 = 1.0f / l0, inv1 = 1.0f / l1;
    int row0 = b * SEQ + q0 + w * 16 + gr;
    size_t o0 = (size_t)row0 * HID + h * HDIM;
    size_t o1 = o0 + 8 * (size_t)HID;
#pragma unroll
    for (int dn = 0; dn < 16; dn++) {
        size_t i0 = o0 + dn * 8 + 2 * tc;
        size_t i1 = o1 + dn * 8 + 2 * tc;
        *(uint32_t*)(g_A16 + i0) = pack_h2(O[dn][0] * inv0, O[dn][1] * inv0);
        *(uint32_t*)(g_A16 + i1) = pack_h2(O[dn][2] * inv1, O[dn][3] * inv1);
    }
}

// ---------------------------------------------------------------------------
// kernel_launch
// ---------------------------------------------------------------------------
extern "C" void kernel_launch(void* const* d_in, const int* in_sizes, int n_in,
                              void* d_out, int out_size) {
    const float* hidden = (const float*)d_in[0];
    const float* past_k = (const float*)d_in[2];
    const float* past_v = (const float*)d_in[3];
    const float* Wq = (const float*)d_in[4];
    const float* bq = (const float*)d_in[5];
    const float* Wk = (const float*)d_in[6];
    const float* bk = (const float*)d_in[7];
    const float* Wv = (const float*)d_in[8];
    const float* bv = (const float*)d_in[9];
    const float* Wo = (const float*)d_in[10];
    const float* bo = (const float*)d_in[11];

    float* out1 = (float*)d_out;
    float* outk = out1 + (size_t)MROWS * HID;
    float* outv = outk + (size_t)BATCH * NHEAD * KVLEN * HDIM;

    void *pqkv, *pbias, *pA16, *pWt, *pWo;
    cudaGetSymbolAddress(&pqkv, g_qkv);
    cudaGetSymbolAddress(&pbias, g_bias6144);
    cudaGetSymbolAddress(&pA16, g_A16);
    cudaGetSymbolAddress(&pWt, g_Wqkvt);
    cudaGetSymbolAddress(&pWo, g_Wot);

    cudaFuncSetAttribute(gemm_fp16_kernel, cudaFuncAttributeMaxDynamicSharedMemorySize, G7_SMEM);
    cudaFuncSetAttribute(attn_mma_kernel, cudaFuncAttributeMaxDynamicSharedMemorySize, ATT_SMEM);

    int n2 = MROWS * HID / 2;

    // 0: convert hidden to fp16
    cvt_fp16_kernel<<<(n2 + 255) / 256, 256>>>((const float2*)hidden, (uint32_t*)pA16, n2);
    // 1: weight transposes + bias concat in one launch
    dim3 tblk(32, 8);
    transpose_cvt4_kernel<<<dim3(HID / 32, HID / 32, 5), tblk>>>(Wq, Wk, Wv, Wo, bq, bk, bv);
    // 2: fused QKV GEMM (fp16, 4-stage, single-sync pipeline)
    dim3 qkvgrid(NQKV / 128, MROWS / 128);
    gemm_fp16_kernel<<<qkvgrid, 128, G7_SMEM>>>((const __half*)pA16, (const __half*)pWt,
                                                (const float*)pbias, (float*)pqkv, NQKV);
    // 3: RoPE + cache assembly
    rope_scatter_kernel<<<SEQ, 256>>>(outk, outv);
    // 4: past copy
    int ncopy = BATCH * NHEAD * PASTL * (HDIM / 4);
    copy_past_kernel<<<(ncopy + 255) / 256, 256>>>((const float4*)past_k, (const float4*)past_v,
                                                   (float4*)outk, (float4*)outv);
    // 5: V transpose/convert
    transpose_cvt_v_kernel<<<dim3(KVLEN / 32, HDIM / 32, BATCH * NHEAD), tblk>>>(outv);
    // 6: attention
    dim3 agrid(SEQ / 128, BATCH * NHEAD);
    attn_mma_kernel<<<agrid, 256, ATT_SMEM>>>();
    // 7: output projection
    dim3 ogrid(HID / 128, MROWS / 128);
    gemm_fp16_kernel<<<ogrid, 128, G7_SMEM>>>((const __half*)pA16, (const __half*)pWo,
                                              bo, out1, HID);
}

// round 15
// speedup vs baseline: 1.1415x; 1.0091x over previous
#include <cuda_runtime.h>
#include <cuda_bf16.h>
#include <cuda_fp16.h>
#include <cstdint>
#include <math.h>

// Problem constants
#define BATCH 2
#define SEQ   1024
#define HID   2048
#define NHEAD 16
#define HDIM  128
#define PASTL 1024
#define KVLEN 2048
#define MROWS 2048
#define NQKV  6144
#define QSCALE 0.08838834764831845f

// ---------------------------------------------------------------------------
// Scratch
// ---------------------------------------------------------------------------
__device__ float g_qkv [MROWS * NQKV];
__device__ float g_bias6144[NQKV];
__device__ __half g_A16[MROWS * HID];
__device__ __half g_Wqkvt[NQKV * HID];
__device__ __half g_Wot[HID * HID];
__device__ __half g_Q16[BATCH * NHEAD * SEQ * HDIM];
__device__ __half g_K16[BATCH * NHEAD * KVLEN * HDIM];
__device__ __half g_V16t[BATCH * NHEAD * HDIM * KVLEN];

// ---------------------------------------------------------------------------
// helpers
// ---------------------------------------------------------------------------
__device__ __forceinline__ uint32_t smem_u32(const void* p) {
    uint32_t a;
    asm("{ .reg .u64 t; cvta.to.shared.u64 t, %1; cvt.u32.u64 %0, t; }" : "=r"(a) : "l"(p));
    return a;
}
__device__ __forceinline__ void cp_async16(uint32_t dst, const void* src) {
    asm volatile("cp.async.cg.shared.global [%0], [%1], 16;" :: "r"(dst), "l"(src));
}
#define CP_ASYNC_COMMIT() asm volatile("cp.async.commit_group;" ::: "memory")
#define CP_ASYNC_WAIT2()  asm volatile("cp.async.wait_group 2;" ::: "memory")
#define CP_ASYNC_WAIT1()  asm volatile("cp.async.wait_group 1;" ::: "memory")
#define CP_ASYNC_WAIT0()  asm volatile("cp.async.wait_group 0;" ::: "memory")

__device__ __forceinline__ void mma_fp16(float& c0, float& c1, float& c2, float& c3,
                                         uint32_t a0, uint32_t a1, uint32_t a2, uint32_t a3,
                                         uint32_t b0, uint32_t b1) {
    asm volatile("mma.sync.aligned.m16n8k16.row.col.f32.f16.f16.f32 "
                 "{%0,%1,%2,%3}, {%4,%5,%6,%7}, {%8,%9}, {%0,%1,%2,%3};"
                 : "+f"(c0), "+f"(c1), "+f"(c2), "+f"(c3)
                 : "r"(a0), "r"(a1), "r"(a2), "r"(a3), "r"(b0), "r"(b1));
}
__device__ __forceinline__ void ldsm_x4(uint32_t* d, uint32_t addr) {
    asm volatile("ldmatrix.sync.aligned.m8n8.x4.shared.b16 {%0,%1,%2,%3}, [%4];"
                 : "=r"(d[0]), "=r"(d[1]), "=r"(d[2]), "=r"(d[3]) : "r"(addr));
}
__device__ __forceinline__ uint32_t pack_h2(float a, float b) {
    __half2 h = __floats2half2_rn(a, b);
    return *(uint32_t*)&h;
}

// ---------------------------------------------------------------------------
// Convert fp32 -> fp16 (packed)
// ---------------------------------------------------------------------------
__global__ void cvt_fp16_kernel(const float2* __restrict__ X, uint32_t* __restrict__ H, int n2) {
    int i = blockIdx.x * blockDim.x + threadIdx.x;
    if (i >= n2) return;
    float2 v = X[i];
    H[i] = pack_h2(v.x, v.y);
}

// ---------------------------------------------------------------------------
// Batched transpose + fp16-convert of 4 weight matrices; z==4 does bias concat
// ---------------------------------------------------------------------------
__global__ void transpose_cvt4_kernel(const float* __restrict__ Wq, const float* __restrict__ Wk,
                                      const float* __restrict__ Wv, const float* __restrict__ Wo,
                                      const float* __restrict__ bq, const float* __restrict__ bk,
                                      const float* __restrict__ bv) {
    if (blockIdx.z == 4) {
        int i = (blockIdx.y * gridDim.x + blockIdx.x) * 256 + threadIdx.y * 32 + threadIdx.x;
        if (i < NQKV)
            g_bias6144[i] = (i < 2048) ? bq[i] : ((i < 4096) ? bk[i - 2048] : bv[i - 4096]);
        return;
    }
    __shared__ float t[32][33];
    const float* W;
    __half* T;
    int nofs;
    switch (blockIdx.z) {
        case 0:  W = Wq; T = g_Wqkvt; nofs = 0;    break;
        case 1:  W = Wk; T = g_Wqkvt; nofs = 2048; break;
        case 2:  W = Wv; T = g_Wqkvt; nofs = 4096; break;
        default: W = Wo; T = g_Wot;   nofs = 0;    break;
    }
    int bx = blockIdx.x * 32;
    int by = blockIdx.y * 32;
    int tx = threadIdx.x, ty = threadIdx.y;
    for (int r = ty; r < 32; r += 8)
        t[r][tx] = W[(size_t)(by + r) * HID + bx + tx];
    __syncthreads();
    for (int r = ty; r < 32; r += 8) {
        float v = t[tx][r];
        T[(size_t)(nofs + bx + r) * HID + by + tx] = __float2half_rn(v);
    }
}

// ---------------------------------------------------------------------------
// fp16 GEMM (unchanged from R14): CTA 128x128, 128 threads, warp tile 64x64,
// BK=32, 4-stage single-sync pipeline, 80 KB smem, 2 CTAs/SM.
// ---------------------------------------------------------------------------
#define G7_PART  10240
#define G7_STAGE (2 * G7_PART)
#define G7_SMEM  (4 * G7_STAGE)

__device__ __forceinline__ void g7_load(const __half* __restrict__ A, const __half* __restrict__ B,
                                        int bm, int bn, int k0, uint32_t st, int tid) {
#pragma unroll
    for (int i = 0; i < 4; i++) {
        int c = i * 128 + tid;
        int row = c >> 2, cc = c & 3;
        cp_async16(st + (uint32_t)(row * 80 + cc * 16),
                   A + (size_t)(bm + row) * HID + k0 + cc * 8);
    }
#pragma unroll
    for (int i = 0; i < 4; i++) {
        int c = i * 128 + tid;
        int row = c >> 2, cc = c & 3;
        cp_async16(st + G7_PART + (uint32_t)(row * 80 + cc * 16),
                   B + (size_t)(bn + row) * HID + k0 + cc * 8);
    }
}

__global__ __launch_bounds__(128, 2)
void gemm_fp16_kernel(const __half* __restrict__ A, const __half* __restrict__ B,
                      const float* __restrict__ bias, float* __restrict__ C, int ldc) {
    extern __shared__ __align__(128) char smem[];
    const uint32_t sb = smem_u32(smem);
    const int tid = threadIdx.x;
    const int w = tid >> 5, lane = tid & 31;
    const int warp_m = w & 1, warp_n = w >> 1;
    const int bm = blockIdx.y * 128, bn = blockIdx.x * 128;
    const int r8 = lane & 7, ti = lane >> 3;
    const int gr = lane >> 2, tc = lane & 3;

    float acc[4][8][4];
#pragma unroll
    for (int a = 0; a < 4; a++)
#pragma unroll
        for (int b = 0; b < 8; b++)
#pragma unroll
            for (int c = 0; c < 4; c++) acc[a][b][c] = 0.f;

#pragma unroll
    for (int s = 0; s < 3; s++) {
        g7_load(A, B, bm, bn, s * 32, sb + s * G7_STAGE, tid);
        CP_ASYNC_COMMIT();
    }

    const int KITERS = HID / 32;
    for (int kt = 0; kt < KITERS; kt++) {
        CP_ASYNC_WAIT2();
        __syncthreads();

        if (kt + 3 < KITERS)
            g7_load(A, B, bm, bn, (kt + 3) * 32, sb + (uint32_t)((kt + 3) & 3) * G7_STAGE, tid);
        CP_ASYNC_COMMIT();

        uint32_t st = sb + (uint32_t)(kt & 3) * G7_STAGE;
#pragma unroll
        for (int ks = 0; ks < 2; ks++) {
            uint32_t bf[4][4];
#pragma unroll
            for (int np = 0; np < 4; np++) {
                uint32_t ba = st + G7_PART +
                              (uint32_t)((warp_n * 64 + np * 16 + r8 + ((ti >> 1) << 3)) * 80 +
                                         (ks * 16 + ((ti & 1) << 3)) * 2);
                ldsm_x4(bf[np], ba);
            }
#pragma unroll
            for (int mi = 0; mi < 4; mi++) {
                uint32_t af[4];
                uint32_t aa = st + (uint32_t)((warp_m * 64 + mi * 16 + r8 + ((ti & 1) << 3)) * 80 +
                                              (ks * 16 + ((ti >> 1) << 3)) * 2);
                ldsm_x4(af, aa);
#pragma unroll
                for (int np = 0; np < 4; np++) {
                    float* c0 = acc[mi][np * 2];
                    float* c1 = acc[mi][np * 2 + 1];
                    mma_fp16(c0[0], c0[1], c0[2], c0[3], af[0], af[1], af[2], af[3],
                             bf[np][0], bf[np][1]);
                    mma_fp16(c1[0], c1[1], c1[2], c1[3], af[0], af[1], af[2], af[3],
                             bf[np][2], bf[np][3]);
                }
            }
        }
    }

#pragma unroll
    for (int j = 0; j < 8; j++) {
        int col = bn + warp_n * 64 + j * 8 + tc * 2;
        float b0 = bias[col], b1 = bias[col + 1];
#pragma unroll
        for (int mi = 0; mi < 4; mi++) {
            int row0 = bm + warp_m * 64 + mi * 16 + gr;
            float* c = acc[mi][j];
            *(float2*)(C + (size_t)row0 * ldc + col) = make_float2(c[0] + b0, c[1] + b1);
            *(float2*)(C + (size_t)(row0 + 8) * ldc + col) = make_float2(c[2] + b0, c[3] + b1);
        }
    }
}

// ---------------------------------------------------------------------------
// Fused prep: blocks [0,1024) RoPE; [1024,5120) past copy; [5120,13312) V-transpose.
// All three parts independent (V-transpose reads g_qkv / past_v directly —
// bit-identical to the outv values).
// ---------------------------------------------------------------------------
__global__ __launch_bounds__(256)
void fused_prep_kernel(const float* __restrict__ pk, const float* __restrict__ pv,
                       float* __restrict__ outk, float* __restrict__ outv) {
    __shared__ float t[32][33];
    const int bid = blockIdx.x;
    const int tid = threadIdx.x;

    if (bid < 1024) {
        // ---- RoPE + scatter (s = bid) ----
        float* cs = &t[0][0];
        float* sn = &t[2][0];
        const int s = bid;
        if (tid < 64) {
            double invf = exp((double)tid * (-9.210340371976184 / 64.0));
            double ang = (double)s * invf;
            cs[tid] = (float)cos(ang);
            sn[tid] = (float)sin(ang);
        }
        __syncthreads();
        for (int e = tid; e < BATCH * NHEAD * 64; e += 256) {
            int d = e & 63;
            int h = (e >> 6) & (NHEAD - 1);
            int b = e >> 10;
            int bh = b * NHEAD + h;
            size_t r = ((size_t)(b * SEQ + s)) * NQKV + (size_t)h * HDIM + d;
            float c = cs[d], si = sn[d];
            float qlo = g_qkv[r],        qhi = g_qkv[r + 64];
            float klo = g_qkv[r + 2048], khi = g_qkv[r + 2048 + 64];

            float q0v = (qlo * c - qhi * si) * QSCALE;
            float q1v = (qhi * c + qlo * si) * QSCALE;
            size_t qo = ((size_t)bh * SEQ + s) * HDIM + d;
            g_Q16[qo]      = __float2half_rn(q0v);
            g_Q16[qo + 64] = __float2half_rn(q1v);

            float k0v = klo * c - khi * si;
            float k1v = khi * c + klo * si;
            size_t ko = ((size_t)bh * KVLEN + PASTL + s) * HDIM + d;
            outk[ko]      = k0v;
            outk[ko + 64] = k1v;
            g_K16[ko]      = __float2half_rn(k0v);
            g_K16[ko + 64] = __float2half_rn(k1v);

            outv[ko]      = g_qkv[r + 4096];
            outv[ko + 64] = g_qkv[r + 4096 + 64];
        }
        return;
    }
    if (bid < 5120) {
        // ---- past K/V copy (float4 granularity) ----
        int i = (bid - 1024) * 256 + tid;
        int col = i & 31;
        int p = (i >> 5) & (PASTL - 1);
        int bh = i >> 15;
        size_t src = ((size_t)bh * PASTL + p) * 32 + col;
        size_t dst = ((size_t)bh * KVLEN + p) * 32 + col;
        float4 kv = ((const float4*)pk)[src];
        ((float4*)outk)[dst] = kv;
        ((float4*)outv)[dst] = ((const float4*)pv)[src];
        uint2 hh = make_uint2(pack_h2(kv.x, kv.y), pack_h2(kv.z, kv.w));
        ((uint2*)g_K16)[dst] = hh;
        return;
    }
    // ---- V transpose + fp16 convert (reads sources directly) ----
    {
        int v = bid - 5120;
        int bh = v >> 8;
        int rem = v & 255;
        int kv0 = (rem & 63) * 32;
        int d0 = (rem >> 6) * 32;
        int b = bh >> 4, h = bh & 15;
        int tx = tid & 31, ty = tid >> 5;   // 8 rows per pass
        for (int r = ty; r < 32; r += 8) {
            int kv = kv0 + r;
            float val;
            if (kv < PASTL)
                val = pv[((size_t)bh * PASTL + kv) * HDIM + d0 + tx];
            else
                val = g_qkv[((size_t)(b * SEQ + kv - PASTL)) * NQKV + h * HDIM + 4096 + d0 + tx];
            t[r][tx] = val;
        }
        __syncthreads();
        __half* dh = g_V16t + (size_t)bh * HDIM * KVLEN;
        for (int r = ty; r < 32; r += 8)
            dh[(size_t)(d0 + r) * KVLEN + kv0 + tx] = __float2half_rn(t[tx][r]);
    }
}

// ---------------------------------------------------------------------------
// Flash attention, fp16 mma.sync, 3-stage single-sync cp.async pipeline.
// ---------------------------------------------------------------------------
#define ATT_KPITCH 272
#define ATT_VPITCH 144
#define ATT_KPART (64 * ATT_KPITCH)
#define ATT_VPART (128 * ATT_VPITCH)
#define ATT_STAGE (ATT_KPART + ATT_VPART)     // 35840
#define ATT_SMEM  (3 * ATT_STAGE)             // 107520
#define QPART 34816

__device__ __forceinline__ void att_load_tile(
    const __half* __restrict__ kg, const __half* __restrict__ vg,
    int kvb, uint32_t st, int tid) {
#pragma unroll
    for (int i = 0; i < 4; i++) {
        int c = i * 256 + tid;
        int row = c >> 4, cc = c & 15;
        cp_async16(st + (uint32_t)(row * ATT_KPITCH + cc * 16),
                   kg + (size_t)(kvb + row) * HDIM + cc * 8);
    }
#pragma unroll
    for (int i = 0; i < 4; i++) {
        int c = i * 256 + tid;
        int row = c >> 3, cc = c & 7;
        cp_async16(st + ATT_KPART + (uint32_t)(row * ATT_VPITCH + cc * 16),
                   vg + (size_t)row * KVLEN + kvb + cc * 8);
    }
}

__global__ __launch_bounds__(256, 1)
void attn_mma_kernel() {
    extern __shared__ __align__(128) char sm[];
    const uint32_t sb = smem_u32(sm);
    const int qt = gridDim.x - 1 - blockIdx.x;
    const int bh = blockIdx.y;
    const int b = bh >> 4, h = bh & 15;
    const int tid = threadIdx.x, w = tid >> 5, lane = tid & 31;
    const int gr = lane >> 2, tc = lane & 3;
    const int r8 = lane & 7, ti = lane >> 3;
    const int q0 = qt * 128;
    const int nt = 18 + 2 * qt;

    const __half* q_g = g_Q16 + ((size_t)bh * SEQ + q0) * HDIM;
    const __half* k_g = g_K16 + (size_t)bh * KVLEN * HDIM;
    const __half* v_g = g_V16t + (size_t)bh * HDIM * KVLEN;

    // stage Q at sb (consumed before tile loads)
#pragma unroll
    for (int i = 0; i < 8; i++) {
        int c = i * 256 + tid;
        int row = c >> 4, cc = c & 15;
        cp_async16(sb + (uint32_t)(row * ATT_KPITCH + cc * 16),
                   q_g + (size_t)row * HDIM + cc * 8);
    }
    CP_ASYNC_COMMIT();
    CP_ASYNC_WAIT0();
    __syncthreads();

    uint32_t qf[8][4];
#pragma unroll
    for (int t = 0; t < 8; t++) {
        uint32_t qa = sb + (uint32_t)((w * 16 + r8 + ((ti & 1) << 3)) * ATT_KPITCH +
                                      (t * 16 + ((ti >> 1) << 3)) * 2);
        ldsm_x4(qf[t], qa);
    }
    __syncthreads();

    // prologue: 2 tiles in flight
    att_load_tile(k_g, v_g, 0, sb, tid);
    CP_ASYNC_COMMIT();
    att_load_tile(k_g, v_g, 64, sb + ATT_STAGE, tid);
    CP_ASYNC_COMMIT();

    float m0 = -1e30f, m1 = -1e30f, l0 = 0.f, l1 = 0.f;
    float O[16][4];
#pragma unroll
    for (int i = 0; i < 16; i++)
#pragma unroll
        for (int c = 0; c < 4; c++) O[i][c] = 0.f;

    int cur = 0, nxt = 2;   // rotating stage indices: compute j%3, load (j+2)%3
    for (int j = 0; j < nt; j++) {
        CP_ASYNC_WAIT1();
        __syncthreads();    // tile j ready; stage nxt free (read at j-1)

        if (j + 2 < nt)
            att_load_tile(k_g, v_g, (j + 2) * 64, sb + (uint32_t)nxt * ATT_STAGE, tid);
        CP_ASYNC_COMMIT();

        uint32_t st = sb + (uint32_t)cur * ATT_STAGE;

        float S[8][4];
#pragma unroll
        for (int i = 0; i < 8; i++)
#pragma unroll
            for (int c = 0; c < 4; c++) S[i][c] = 0.f;

        const uint32_t kbase = st + (uint32_t)((r8 + ((ti >> 1) << 3)) * ATT_KPITCH +
                                               ((ti & 1) << 3) * 2);
#pragma unroll
        for (int kt = 0; kt < 8; kt++) {
#pragma unroll
            for (int p = 0; p < 4; p++) {
                uint32_t kb[4];
                ldsm_x4(kb, kbase + (uint32_t)(p * 16 * ATT_KPITCH + kt * 32));
                mma_fp16(S[2*p][0], S[2*p][1], S[2*p][2], S[2*p][3],
                         qf[kt][0], qf[kt][1], qf[kt][2], qf[kt][3], kb[0], kb[1]);
                mma_fp16(S[2*p+1][0], S[2*p+1][1], S[2*p+1][2], S[2*p+1][3],
                         qf[kt][0], qf[kt][1], qf[kt][2], qf[kt][3], kb[2], kb[3]);
            }
        }

        if (j >= nt - 2) {
            int qp0 = PASTL + q0 + w * 16 + gr;
#pragma unroll
            for (int i = 0; i < 8; i++) {
                int kvp = j * 64 + i * 8 + 2 * tc;
                if (kvp > qp0)         S[i][0] = -1e30f;
                if (kvp + 1 > qp0)     S[i][1] = -1e30f;
                if (kvp > qp0 + 8)     S[i][2] = -1e30f;
                if (kvp + 1 > qp0 + 8) S[i][3] = -1e30f;
            }
        }

        float mx0 = -1e30f, mx1 = -1e30f;
#pragma unroll
        for (int i = 0; i < 8; i++) {
            mx0 = fmaxf(mx0, fmaxf(S[i][0], S[i][1]));
            mx1 = fmaxf(mx1, fmaxf(S[i][2], S[i][3]));
        }
        mx0 = fmaxf(mx0, __shfl_xor_sync(0xffffffffu, mx0, 1));
        mx0 = fmaxf(mx0, __shfl_xor_sync(0xffffffffu, mx0, 2));
        mx1 = fmaxf(mx1, __shfl_xor_sync(0xffffffffu, mx1, 1));
        mx1 = fmaxf(mx1, __shfl_xor_sync(0xffffffffu, mx1, 2));
        float mn0 = fmaxf(m0, mx0), mn1 = fmaxf(m1, mx1);
        float a0 = __expf(m0 - mn0), a1 = __expf(m1 - mn1);
        m0 = mn0; m1 = mn1;

        float rs0 = 0.f, rs1 = 0.f;
        uint32_t pp[4][4];
#pragma unroll
        for (int i = 0; i < 8; i++) {
            float p0 = __expf(S[i][0] - mn0), p1 = __expf(S[i][1] - mn0);
            float p2 = __expf(S[i][2] - mn1), p3 = __expf(S[i][3] - mn1);
            rs0 += p0 + p1;
            rs1 += p2 + p3;
            int kvk = i >> 1, sel = (i & 1) * 2;
            pp[kvk][sel]     = pack_h2(p0, p1);
            pp[kvk][sel + 1] = pack_h2(p2, p3);
        }
        rs0 += __shfl_xor_sync(0xffffffffu, rs0, 1);
        rs0 += __shfl_xor_sync(0xffffffffu, rs0, 2);
        rs1 += __shfl_xor_sync(0xffffffffu, rs1, 1);
        rs1 += __shfl_xor_sync(0xffffffffu, rs1, 2);
        l0 = l0 * a0 + rs0;
        l1 = l1 * a1 + rs1;
#pragma unroll
        for (int i = 0; i < 16; i++) {
            O[i][0] *= a0; O[i][1] *= a0;
            O[i][2] *= a1; O[i][3] *= a1;
        }

        const uint32_t vbase = st + ATT_KPART +
                               (uint32_t)((r8 + ((ti >> 1) << 3)) * ATT_VPITCH +
                                          ((ti & 1) << 3) * 2);
#pragma unroll
        for (int kvk = 0; kvk < 4; kvk++) {
#pragma unroll
            for (int p = 0; p < 8; p++) {
                uint32_t vb[4];
                ldsm_x4(vb, vbase + (uint32_t)(p * 16 * ATT_VPITCH + kvk * 32));
                mma_fp16(O[2*p][0], O[2*p][1], O[2*p][2], O[2*p][3],
                         pp[kvk][0], pp[kvk][1], pp[kvk][2], pp[kvk][3], vb[0], vb[1]);
                mma_fp16(O[2*p+1][0], O[2*p+1][1], O[2*p+1][2], O[2*p+1][3],
                         pp[kvk][0], pp[kvk][1], pp[kvk][2], pp[kvk][3], vb[2], vb[3]);
            }
        }

        cur = (cur == 2) ? 0 : cur + 1;
        nxt = (nxt == 2) ? 0 : nxt + 1;
    }

    float inv0 = 1.0f / l0, inv1 = 1.0f / l1;
    int row0 = b * SEQ + q0 + w * 16 + gr;
    size_t o0 = (size_t)row0 * HID + h * HDIM;
    size_t o1 = o0 + 8 * (size_t)HID;
#pragma unroll
    for (int dn = 0; dn < 16; dn++) {
        size_t i0 = o0 + dn * 8 + 2 * tc;
        size_t i1 = o1 + dn * 8 + 2 * tc;
        *(uint32_t*)(g_A16 + i0) = pack_h2(O[dn][0] * inv0, O[dn][1] * inv0);
        *(uint32_t*)(g_A16 + i1) = pack_h2(O[dn][2] * inv1, O[dn][3] * inv1);
    }
}

// ---------------------------------------------------------------------------
// kernel_launch
// ---------------------------------------------------------------------------
extern "C" void kernel_launch(void* const* d_in, const int* in_sizes, int n_in,
                              void* d_out, int out_size) {
    const float* hidden = (const float*)d_in[0];
    const float* past_k = (const float*)d_in[2];
    const float* past_v = (const float*)d_in[3];
    const float* Wq = (const float*)d_in[4];
    const float* bq = (const float*)d_in[5];
    const float* Wk = (const float*)d_in[6];
    const float* bk = (const float*)d_in[7];
    const float* Wv = (const float*)d_in[8];
    const float* bv = (const float*)d_in[9];
    const float* Wo = (const float*)d_in[10];
    const float* bo = (const float*)d_in[11];

    float* out1 = (float*)d_out;
    float* outk = out1 + (size_t)MROWS * HID;
    float* outv = outk + (size_t)BATCH * NHEAD * KVLEN * HDIM;

    void *pqkv, *pbias, *pA16, *pWt, *pWo;
    cudaGetSymbolAddress(&pqkv, g_qkv);
    cudaGetSymbolAddress(&pbias, g_bias6144);
    cudaGetSymbolAddress(&pA16, g_A16);
    cudaGetSymbolAddress(&pWt, g_Wqkvt);
    cudaGetSymbolAddress(&pWo, g_Wot);

    cudaFuncSetAttribute(gemm_fp16_kernel, cudaFuncAttributeMaxDynamicSharedMemorySize, G7_SMEM);
    cudaFuncSetAttribute(attn_mma_kernel, cudaFuncAttributeMaxDynamicSharedMemorySize, ATT_SMEM);

    int n2 = MROWS * HID / 2;

    // 0: convert hidden to fp16
    cvt_fp16_kernel<<<(n2 + 255) / 256, 256>>>((const float2*)hidden, (uint32_t*)pA16, n2);
    // 1: weight transposes + bias concat
    dim3 tblk(32, 8);
    transpose_cvt4_kernel<<<dim3(HID / 32, HID / 32, 5), tblk>>>(Wq, Wk, Wv, Wo, bq, bk, bv);
    // 2: fused QKV GEMM
    dim3 qkvgrid(NQKV / 128, MROWS / 128);
    gemm_fp16_kernel<<<qkvgrid, 128, G7_SMEM>>>((const __half*)pA16, (const __half*)pWt,
                                                (const float*)pbias, (float*)pqkv, NQKV);
    // 3: fused prep (rope + past copy + V transpose)
    fused_prep_kernel<<<13312, 256>>>(past_k, past_v, outk, outv);
    // 4: attention (3-stage single-sync)
    dim3 agrid(SEQ / 128, BATCH * NHEAD);
    attn_mma_kernel<<<agrid, 256, ATT_SMEM>>>();
    // 5: output projection
    dim3 ogrid(HID / 128, MROWS / 128);
    gemm_fp16_kernel<<<ogrid, 128, G7_SMEM>>>((const __half*)pA16, (const __half*)pWo,
                                              bo, out1, HID);
}

// round 16
// speedup vs baseline: 1.1827x; 1.0361x over previous
#include <cuda_runtime.h>
#include <cuda_bf16.h>
#include <cuda_fp16.h>
#include <cstdint>
#include <math.h>

// Problem constants
#define BATCH 2
#define SEQ   1024
#define HID   2048
#define NHEAD 16
#define HDIM  128
#define PASTL 1024
#define KVLEN 2048
#define MROWS 2048
#define NQKV  6144
#define QSCALE 0.08838834764831845f

// ---------------------------------------------------------------------------
// Scratch
// ---------------------------------------------------------------------------
__device__ float g_qkv [MROWS * NQKV];
__device__ float g_bias6144[NQKV];
__device__ __half g_A16[MROWS * HID];
__device__ __half g_Wqkvt[NQKV * HID];
__device__ __half g_Wot[HID * HID];
__device__ __half g_Q16[BATCH * NHEAD * SEQ * HDIM];
__device__ __half g_K16[BATCH * NHEAD * KVLEN * HDIM];
__device__ __half g_V16t[BATCH * NHEAD * HDIM * KVLEN];

// ---------------------------------------------------------------------------
// helpers
// ---------------------------------------------------------------------------
__device__ __forceinline__ uint32_t smem_u32(const void* p) {
    uint32_t a;
    asm("{ .reg .u64 t; cvta.to.shared.u64 t, %1; cvt.u32.u64 %0, t; }" : "=r"(a) : "l"(p));
    return a;
}
__device__ __forceinline__ void cp_async16(uint32_t dst, const void* src) {
    asm volatile("cp.async.cg.shared.global [%0], [%1], 16;" :: "r"(dst), "l"(src));
}
#define CP_ASYNC_COMMIT() asm volatile("cp.async.commit_group;" ::: "memory")
#define CP_ASYNC_WAIT2()  asm volatile("cp.async.wait_group 2;" ::: "memory")
#define CP_ASYNC_WAIT1()  asm volatile("cp.async.wait_group 1;" ::: "memory")
#define CP_ASYNC_WAIT0()  asm volatile("cp.async.wait_group 0;" ::: "memory")

__device__ __forceinline__ void mma_fp16(float& c0, float& c1, float& c2, float& c3,
                                         uint32_t a0, uint32_t a1, uint32_t a2, uint32_t a3,
                                         uint32_t b0, uint32_t b1) {
    asm volatile("mma.sync.aligned.m16n8k16.row.col.f32.f16.f16.f32 "
                 "{%0,%1,%2,%3}, {%4,%5,%6,%7}, {%8,%9}, {%0,%1,%2,%3};"
                 : "+f"(c0), "+f"(c1), "+f"(c2), "+f"(c3)
                 : "r"(a0), "r"(a1), "r"(a2), "r"(a3), "r"(b0), "r"(b1));
}
__device__ __forceinline__ void ldsm_x4(uint32_t* d, uint32_t addr) {
    asm volatile("ldmatrix.sync.aligned.m8n8.x4.shared.b16 {%0,%1,%2,%3}, [%4];"
                 : "=r"(d[0]), "=r"(d[1]), "=r"(d[2]), "=r"(d[3]) : "r"(addr));
}
__device__ __forceinline__ uint32_t pack_h2(float a, float b) {
    __half2 h = __floats2half2_rn(a, b);
    return *(uint32_t*)&h;
}

// ---------------------------------------------------------------------------
// Weight transposes (z=0..3) + hidden fp16 cvt (z=4) + bias concat (z=5)
// ---------------------------------------------------------------------------
__global__ void prep_weights_kernel(const float* __restrict__ Wq, const float* __restrict__ Wk,
                                    const float* __restrict__ Wv, const float* __restrict__ Wo,
                                    const float* __restrict__ bq, const float* __restrict__ bk,
                                    const float* __restrict__ bv,
                                    const float* __restrict__ hidden) {
    const int z = blockIdx.z;
    if (z == 4) {
        // cvt hidden -> fp16: 4096 blocks x 256 threads x 2 float2 = 2M float2
        int i = ((blockIdx.y * gridDim.x + blockIdx.x) * 256 + threadIdx.y * 32 + threadIdx.x) * 2;
        const float2* X = (const float2*)hidden;
        uint32_t* H = (uint32_t*)g_A16;
        float2 v0 = X[i], v1 = X[i + 1];
        H[i]     = pack_h2(v0.x, v0.y);
        H[i + 1] = pack_h2(v1.x, v1.y);
        return;
    }
    if (z == 5) {
        int i = (blockIdx.y * gridDim.x + blockIdx.x) * 256 + threadIdx.y * 32 + threadIdx.x;
        if (i < NQKV)
            g_bias6144[i] = (i < 2048) ? bq[i] : ((i < 4096) ? bk[i - 2048] : bv[i - 4096]);
        return;
    }
    __shared__ float t[32][33];
    const float* W;
    __half* T;
    int nofs;
    switch (z) {
        case 0:  W = Wq; T = g_Wqkvt; nofs = 0;    break;
        case 1:  W = Wk; T = g_Wqkvt; nofs = 2048; break;
        case 2:  W = Wv; T = g_Wqkvt; nofs = 4096; break;
        default: W = Wo; T = g_Wot;   nofs = 0;    break;
    }
    int bx = blockIdx.x * 32;
    int by = blockIdx.y * 32;
    int tx = threadIdx.x, ty = threadIdx.y;
    for (int r = ty; r < 32; r += 8)
        t[r][tx] = W[(size_t)(by + r) * HID + bx + tx];
    __syncthreads();
    for (int r = ty; r < 32; r += 8) {
        float v = t[tx][r];
        T[(size_t)(nofs + bx + r) * HID + by + tx] = __float2half_rn(v);
    }
}

// ---------------------------------------------------------------------------
// fp16 GEMM (unchanged from R14): CTA 128x128, 128 threads, warp tile 64x64,
// BK=32, 4-stage single-sync pipeline, 80 KB smem, 2 CTAs/SM.
// ---------------------------------------------------------------------------
#define G7_PART  10240
#define G7_STAGE (2 * G7_PART)
#define G7_SMEM  (4 * G7_STAGE)

__device__ __forceinline__ void g7_load(const __half* __restrict__ A, const __half* __restrict__ B,
                                        int bm, int bn, int k0, uint32_t st, int tid) {
#pragma unroll
    for (int i = 0; i < 4; i++) {
        int c = i * 128 + tid;
        int row = c >> 2, cc = c & 3;
        cp_async16(st + (uint32_t)(row * 80 + cc * 16),
                   A + (size_t)(bm + row) * HID + k0 + cc * 8);
    }
#pragma unroll
    for (int i = 0; i < 4; i++) {
        int c = i * 128 + tid;
        int row = c >> 2, cc = c & 3;
        cp_async16(st + G7_PART + (uint32_t)(row * 80 + cc * 16),
                   B + (size_t)(bn + row) * HID + k0 + cc * 8);
    }
}

__global__ __launch_bounds__(128, 2)
void gemm_fp16_kernel(const __half* __restrict__ A, const __half* __restrict__ B,
                      const float* __restrict__ bias, float* __restrict__ C, int ldc) {
    extern __shared__ __align__(128) char smem[];
    const uint32_t sb = smem_u32(smem);
    const int tid = threadIdx.x;
    const int w = tid >> 5, lane = tid & 31;
    const int warp_m = w & 1, warp_n = w >> 1;
    const int bm = blockIdx.y * 128, bn = blockIdx.x * 128;
    const int r8 = lane & 7, ti = lane >> 3;
    const int gr = lane >> 2, tc = lane & 3;

    float acc[4][8][4];
#pragma unroll
    for (int a = 0; a < 4; a++)
#pragma unroll
        for (int b = 0; b < 8; b++)
#pragma unroll
            for (int c = 0; c < 4; c++) acc[a][b][c] = 0.f;

#pragma unroll
    for (int s = 0; s < 3; s++) {
        g7_load(A, B, bm, bn, s * 32, sb + s * G7_STAGE, tid);
        CP_ASYNC_COMMIT();
    }

    const int KITERS = HID / 32;
    for (int kt = 0; kt < KITERS; kt++) {
        CP_ASYNC_WAIT2();
        __syncthreads();

        if (kt + 3 < KITERS)
            g7_load(A, B, bm, bn, (kt + 3) * 32, sb + (uint32_t)((kt + 3) & 3) * G7_STAGE, tid);
        CP_ASYNC_COMMIT();

        uint32_t st = sb + (uint32_t)(kt & 3) * G7_STAGE;
#pragma unroll
        for (int ks = 0; ks < 2; ks++) {
            uint32_t bf[4][4];
#pragma unroll
            for (int np = 0; np < 4; np++) {
                uint32_t ba = st + G7_PART +
                              (uint32_t)((warp_n * 64 + np * 16 + r8 + ((ti >> 1) << 3)) * 80 +
                                         (ks * 16 + ((ti & 1) << 3)) * 2);
                ldsm_x4(bf[np], ba);
            }
#pragma unroll
            for (int mi = 0; mi < 4; mi++) {
                uint32_t af[4];
                uint32_t aa = st + (uint32_t)((warp_m * 64 + mi * 16 + r8 + ((ti & 1) << 3)) * 80 +
                                              (ks * 16 + ((ti >> 1) << 3)) * 2);
                ldsm_x4(af, aa);
#pragma unroll
                for (int np = 0; np < 4; np++) {
                    float* c0 = acc[mi][np * 2];
                    float* c1 = acc[mi][np * 2 + 1];
                    mma_fp16(c0[0], c0[1], c0[2], c0[3], af[0], af[1], af[2], af[3],
                             bf[np][0], bf[np][1]);
                    mma_fp16(c1[0], c1[1], c1[2], c1[3], af[0], af[1], af[2], af[3],
                             bf[np][2], bf[np][3]);
                }
            }
        }
    }

#pragma unroll
    for (int j = 0; j < 8; j++) {
        int col = bn + warp_n * 64 + j * 8 + tc * 2;
        float b0 = bias[col], b1 = bias[col + 1];
#pragma unroll
        for (int mi = 0; mi < 4; mi++) {
            int row0 = bm + warp_m * 64 + mi * 16 + gr;
            float* c = acc[mi][j];
            *(float2*)(C + (size_t)row0 * ldc + col) = make_float2(c[0] + b0, c[1] + b1);
            *(float2*)(C + (size_t)(row0 + 8) * ldc + col) = make_float2(c[2] + b0, c[3] + b1);
        }
    }
}

// ---------------------------------------------------------------------------
// Fused prep: blocks [0,1024) RoPE (k,q; no outv); [1024,5120) past K copy;
// [5120,13312) V transpose (writes outv for BOTH regions — coalesced).
// ---------------------------------------------------------------------------
__global__ __launch_bounds__(256)
void fused_prep_kernel(const float* __restrict__ pk, const float* __restrict__ pv,
                       float* __restrict__ outk, float* __restrict__ outv) {
    __shared__ float t[32][33];
    const int bid = blockIdx.x;
    const int tid = threadIdx.x;

    if (bid < 1024) {
        // ---- RoPE + scatter (s = bid) ----
        float* cs = &t[0][0];
        float* sn = &t[2][0];
        const int s = bid;
        if (tid < 64) {
            double invf = exp((double)tid * (-9.210340371976184 / 64.0));
            double ang = (double)s * invf;
            cs[tid] = (float)cos(ang);
            sn[tid] = (float)sin(ang);
        }
        __syncthreads();
        for (int e = tid; e < BATCH * NHEAD * 64; e += 256) {
            int d = e & 63;
            int h = (e >> 6) & (NHEAD - 1);
            int b = e >> 10;
            int bh = b * NHEAD + h;
            size_t r = ((size_t)(b * SEQ + s)) * NQKV + (size_t)h * HDIM + d;
            float c = cs[d], si = sn[d];
            float qlo = g_qkv[r],        qhi = g_qkv[r + 64];
            float klo = g_qkv[r + 2048], khi = g_qkv[r + 2048 + 64];

            float q0v = (qlo * c - qhi * si) * QSCALE;
            float q1v = (qhi * c + qlo * si) * QSCALE;
            size_t qo = ((size_t)bh * SEQ + s) * HDIM + d;
            g_Q16[qo]      = __float2half_rn(q0v);
            g_Q16[qo + 64] = __float2half_rn(q1v);

            float k0v = klo * c - khi * si;
            float k1v = khi * c + klo * si;
            size_t ko = ((size_t)bh * KVLEN + PASTL + s) * HDIM + d;
            outk[ko]      = k0v;
            outk[ko + 64] = k1v;
            g_K16[ko]      = __float2half_rn(k0v);
            g_K16[ko + 64] = __float2half_rn(k1v);
        }
        return;
    }
    if (bid < 5120) {
        // ---- past K copy (float4) + fp16 K cache ----
        int i = (bid - 1024) * 256 + tid;
        int col = i & 31;
        int p = (i >> 5) & (PASTL - 1);
        int bh = i >> 15;
        size_t src = ((size_t)bh * PASTL + p) * 32 + col;
        size_t dst = ((size_t)bh * KVLEN + p) * 32 + col;
        float4 kv = ((const float4*)pk)[src];
        ((float4*)outk)[dst] = kv;
        uint2 hh = make_uint2(pack_h2(kv.x, kv.y), pack_h2(kv.z, kv.w));
        ((uint2*)g_K16)[dst] = hh;
        return;
    }
    // ---- V transpose + fp16 convert + outv write (both regions) ----
    {
        int v = bid - 5120;
        int bh = v >> 8;
        int rem = v & 255;
        int kv0 = (rem & 63) * 32;
        int d0 = (rem >> 6) * 32;
        int b = bh >> 4, h = bh & 15;
        int tx = tid & 31, ty = tid >> 5;
        float* ov = outv + (size_t)bh * KVLEN * HDIM;
        for (int r = ty; r < 32; r += 8) {
            int kv = kv0 + r;
            float val;
            if (kv < PASTL)
                val = pv[((size_t)bh * PASTL + kv) * HDIM + d0 + tx];
            else
                val = g_qkv[((size_t)(b * SEQ + kv - PASTL)) * NQKV + h * HDIM + 4096 + d0 + tx];
            t[r][tx] = val;
            ov[(size_t)kv * HDIM + d0 + tx] = val;   // coalesced outv write
        }
        __syncthreads();
        __half* dh = g_V16t + (size_t)bh * HDIM * KVLEN;
        for (int r = ty; r < 32; r += 8)
            dh[(size_t)(d0 + r) * KVLEN + kv0 + tx] = __float2half_rn(t[tx][r]);
    }
}

// ---------------------------------------------------------------------------
// Flash attention, fp16 mma.sync, 3-stage single-sync cp.async pipeline.
// ---------------------------------------------------------------------------
#define ATT_KPITCH 272
#define ATT_VPITCH 144
#define ATT_KPART (64 * ATT_KPITCH)
#define ATT_VPART (128 * ATT_VPITCH)
#define ATT_STAGE (ATT_KPART + ATT_VPART)
#define ATT_SMEM  (3 * ATT_STAGE)

__device__ __forceinline__ void att_load_tile(
    const __half* __restrict__ kg, const __half* __restrict__ vg,
    int kvb, uint32_t st, int tid) {
#pragma unroll
    for (int i = 0; i < 4; i++) {
        int c = i * 256 + tid;
        int row = c >> 4, cc = c & 15;
        cp_async16(st + (uint32_t)(row * ATT_KPITCH + cc * 16),
                   kg + (size_t)(kvb + row) * HDIM + cc * 8);
    }
#pragma unroll
    for (int i = 0; i < 4; i++) {
        int c = i * 256 + tid;
        int row = c >> 3, cc = c & 7;
        cp_async16(st + ATT_KPART + (uint32_t)(row * ATT_VPITCH + cc * 16),
                   vg + (size_t)row * KVLEN + kvb + cc * 8);
    }
}

__global__ __launch_bounds__(256, 1)
void attn_mma_kernel() {
    extern __shared__ __align__(128) char sm[];
    const uint32_t sb = smem_u32(sm);
    const int qt = gridDim.x - 1 - blockIdx.x;
    const int bh = blockIdx.y;
    const int b = bh >> 4, h = bh & 15;
    const int tid = threadIdx.x, w = tid >> 5, lane = tid & 31;
    const int gr = lane >> 2, tc = lane & 3;
    const int r8 = lane & 7, ti = lane >> 3;
    const int q0 = qt * 128;
    const int nt = 18 + 2 * qt;

    const __half* q_g = g_Q16 + ((size_t)bh * SEQ + q0) * HDIM;
    const __half* k_g = g_K16 + (size_t)bh * KVLEN * HDIM;
    const __half* v_g = g_V16t + (size_t)bh * HDIM * KVLEN;

#pragma unroll
    for (int i = 0; i < 8; i++) {
        int c = i * 256 + tid;
        int row = c >> 4, cc = c & 15;
        cp_async16(sb + (uint32_t)(row * ATT_KPITCH + cc * 16),
                   q_g + (size_t)row * HDIM + cc * 8);
    }
    CP_ASYNC_COMMIT();
    CP_ASYNC_WAIT0();
    __syncthreads();

    uint32_t qf[8][4];
#pragma unroll
    for (int t = 0; t < 8; t++) {
        uint32_t qa = sb + (uint32_t)((w * 16 + r8 + ((ti & 1) << 3)) * ATT_KPITCH +
                                      (t * 16 + ((ti >> 1) << 3)) * 2);
        ldsm_x4(qf[t], qa);
    }
    __syncthreads();

    att_load_tile(k_g, v_g, 0, sb, tid);
    CP_ASYNC_COMMIT();
    att_load_tile(k_g, v_g, 64, sb + ATT_STAGE, tid);
    CP_ASYNC_COMMIT();

    float m0 = -1e30f, m1 = -1e30f, l0 = 0.f, l1 = 0.f;
    float O[16][4];
#pragma unroll
    for (int i = 0; i < 16; i++)
#pragma unroll
        for (int c = 0; c < 4; c++) O[i][c] = 0.f;

    int cur = 0, nxt = 2;
    for (int j = 0; j < nt; j++) {
        CP_ASYNC_WAIT1();
        __syncthreads();

        if (j + 2 < nt)
            att_load_tile(k_g, v_g, (j + 2) * 64, sb + (uint32_t)nxt * ATT_STAGE, tid);
        CP_ASYNC_COMMIT();

        uint32_t st = sb + (uint32_t)cur * ATT_STAGE;

        float S[8][4];
#pragma unroll
        for (int i = 0; i < 8; i++)
#pragma unroll
            for (int c = 0; c < 4; c++) S[i][c] = 0.f;

        const uint32_t kbase = st + (uint32_t)((r8 + ((ti >> 1) << 3)) * ATT_KPITCH +
                                               ((ti & 1) << 3) * 2);
#pragma unroll
        for (int kt = 0; kt < 8; kt++) {
#pragma unroll
            for (int p = 0; p < 4; p++) {
                uint32_t kb[4];
                ldsm_x4(kb, kbase + (uint32_t)(p * 16 * ATT_KPITCH + kt * 32));
                mma_fp16(S[2*p][0], S[2*p][1], S[2*p][2], S[2*p][3],
                         qf[kt][0], qf[kt][1], qf[kt][2], qf[kt][3], kb[0], kb[1]);
                mma_fp16(S[2*p+1][0], S[2*p+1][1], S[2*p+1][2], S[2*p+1][3],
                         qf[kt][0], qf[kt][1], qf[kt][2], qf[kt][3], kb[2], kb[3]);
            }
        }

        if (j >= nt - 2) {
            int qp0 = PASTL + q0 + w * 16 + gr;
#pragma unroll
            for (int i = 0; i < 8; i++) {
                int kvp = j * 64 + i * 8 + 2 * tc;
                if (kvp > qp0)         S[i][0] = -1e30f;
                if (kvp + 1 > qp0)     S[i][1] = -1e30f;
                if (kvp > qp0 + 8)     S[i][2] = -1e30f;
                if (kvp + 1 > qp0 + 8) S[i][3] = -1e30f;
            }
        }

        float mx0 = -1e30f, mx1 = -1e30f;
#pragma unroll
        for (int i = 0; i < 8; i++) {
            mx0 = fmaxf(mx0, fmaxf(S[i][0], S[i][1]));
            mx1 = fmaxf(mx1, fmaxf(S[i][2], S[i][3]));
        }
        mx0 = fmaxf(mx0, __shfl_xor_sync(0xffffffffu, mx0, 1));
        mx0 = fmaxf(mx0, __shfl_xor_sync(0xffffffffu, mx0, 2));
        mx1 = fmaxf(mx1, __shfl_xor_sync(0xffffffffu, mx1, 1));
        mx1 = fmaxf(mx1, __shfl_xor_sync(0xffffffffu, mx1, 2));
        float mn0 = fmaxf(m0, mx0), mn1 = fmaxf(m1, mx1);
        float a0 = __expf(m0 - mn0), a1 = __expf(m1 - mn1);
        m0 = mn0; m1 = mn1;

        float rs0 = 0.f, rs1 = 0.f;
        uint32_t pp[4][4];
#pragma unroll
        for (int i = 0; i < 8; i++) {
            float p0 = __expf(S[i][0] - mn0), p1 = __expf(S[i][1] - mn0);
            float p2 = __expf(S[i][2] - mn1), p3 = __expf(S[i][3] - mn1);
            rs0 += p0 + p1;
            rs1 += p2 + p3;
            int kvk = i >> 1, sel = (i & 1) * 2;
            pp[kvk][sel]     = pack_h2(p0, p1);
            pp[kvk][sel + 1] = pack_h2(p2, p3);
        }
        rs0 += __shfl_xor_sync(0xffffffffu, rs0, 1);
        rs0 += __shfl_xor_sync(0xffffffffu, rs0, 2);
        rs1 += __shfl_xor_sync(0xffffffffu, rs1, 1);
        rs1 += __shfl_xor_sync(0xffffffffu, rs1, 2);
        l0 = l0 * a0 + rs0;
        l1 = l1 * a1 + rs1;
#pragma unroll
        for (int i = 0; i < 16; i++) {
            O[i][0] *= a0; O[i][1] *= a0;
            O[i][2] *= a1; O[i][3] *= a1;
        }

        const uint32_t vbase = st + ATT_KPART +
                               (uint32_t)((r8 + ((ti >> 1) << 3)) * ATT_VPITCH +
                                          ((ti & 1) << 3) * 2);
#pragma unroll
        for (int kvk = 0; kvk < 4; kvk++) {
#pragma unroll
            for (int p = 0; p < 8; p++) {
                uint32_t vb[4];
                ldsm_x4(vb, vbase + (uint32_t)(p * 16 * ATT_VPITCH + kvk * 32));
                mma_fp16(O[2*p][0], O[2*p][1], O[2*p][2], O[2*p][3],
                         pp[kvk][0], pp[kvk][1], pp[kvk][2], pp[kvk][3], vb[0], vb[1]);
                mma_fp16(O[2*p+1][0], O[2*p+1][1], O[2*p+1][2], O[2*p+1][3],
                         pp[kvk][0], pp[kvk][1], pp[kvk][2], pp[kvk][3], vb[2], vb[3]);
            }
        }

        cur = (cur == 2) ? 0 : cur + 1;
        nxt = (nxt == 2) ? 0 : nxt + 1;
    }

    float inv0 = 1.0f / l0, inv1 = 1.0f / l1;
    int row0 = b * SEQ + q0 + w * 16 + gr;
    size_t o0 = (size_t)row0 * HID + h * HDIM;
    size_t o1 = o0 + 8 * (size_t)HID;
#pragma unroll
    for (int dn = 0; dn < 16; dn++) {
        size_t i0 = o0 + dn * 8 + 2 * tc;
        size_t i1 = o1 + dn * 8 + 2 * tc;
        *(uint32_t*)(g_A16 + i0) = pack_h2(O[dn][0] * inv0, O[dn][1] * inv0);
        *(uint32_t*)(g_A16 + i1) = pack_h2(O[dn][2] * inv1, O[dn][3] * inv1);
    }
}

// ---------------------------------------------------------------------------
// kernel_launch
// ---------------------------------------------------------------------------
extern "C" void kernel_launch(void* const* d_in, const int* in_sizes, int n_in,
                              void* d_out, int out_size) {
    const float* hidden = (const float*)d_in[0];
    const float* past_k = (const float*)d_in[2];
    const float* past_v = (const float*)d_in[3];
    const float* Wq = (const float*)d_in[4];
    const float* bq = (const float*)d_in[5];
    const float* Wk = (const float*)d_in[6];
    const float* bk = (const float*)d_in[7];
    const float* Wv = (const float*)d_in[8];
    const float* bv = (const float*)d_in[9];
    const float* Wo = (const float*)d_in[10];
    const float* bo = (const float*)d_in[11];

    float* out1 = (float*)d_out;
    float* outk = out1 + (size_t)MROWS * HID;
    float* outv = outk + (size_t)BATCH * NHEAD * KVLEN * HDIM;

    void *pqkv, *pbias, *pA16, *pWt, *pWo;
    cudaGetSymbolAddress(&pqkv, g_qkv);
    cudaGetSymbolAddress(&pbias, g_bias6144);
    cudaGetSymbolAddress(&pA16, g_A16);
    cudaGetSymbolAddress(&pWt, g_Wqkvt);
    cudaGetSymbolAddress(&pWo, g_Wot);

    cudaFuncSetAttribute(gemm_fp16_kernel, cudaFuncAttributeMaxDynamicSharedMemorySize, G7_SMEM);
    cudaFuncSetAttribute(attn_mma_kernel, cudaFuncAttributeMaxDynamicSharedMemorySize, ATT_SMEM);

    // 0: weights transpose + hidden cvt + bias (one launch)
    dim3 tblk(32, 8);
    prep_weights_kernel<<<dim3(HID / 32, HID / 32, 6), tblk>>>(Wq, Wk, Wv, Wo, bq, bk, bv, hidden);
    // 1: fused QKV GEMM
    dim3 qkvgrid(NQKV / 128, MROWS / 128);
    gemm_fp16_kernel<<<qkvgrid, 128, G7_SMEM>>>((const __half*)pA16, (const __half*)pWt,
                                                (const float*)pbias, (float*)pqkv, NQKV);
    // 2: fused prep (rope + past K copy + V transpose/outv)
    fused_prep_kernel<<<13312, 256>>>(past_k, past_v, outk, outv);
    // 3: attention
    dim3 agrid(SEQ / 128, BATCH * NHEAD);
    attn_mma_kernel<<<agrid, 256, ATT_SMEM>>>();
    // 4: output projection
    dim3 ogrid(HID / 128, MROWS / 128);
    gemm_fp16_kernel<<<ogrid, 128, G7_SMEM>>>((const __half*)pA16, (const __half*)pWo,
                                              bo, out1, HID);
}